// round 6
// baseline (speedup 1.0000x reference)
#include <cuda_runtime.h>
#include <cuda_bf16.h>
#include <math.h>
#include <cstdint>

#define NN 32768
#define NE 49152
#define NB 1024
#define DD 64

// ---------------- device scratch (no allocations allowed) ----------------
__device__ __nv_bfloat16 g_h1[(size_t)NE * 128];    // edge MLP hidden (bf16)
__device__ __nv_bfloat16 g_e2[4096 * 128];          // e2_W (bf16)
__device__ __nv_bfloat16 g_Wb[(size_t)NE * 4096];   // edge weights (bf16, 402 MB)
__device__ float g_out[NN * DD];                    // node features / GRU h
__device__ float g_m[NN * DD];                      // conv output m
__device__ float g_agg[NN * DD];                    // message accumulator
__device__ float g_cnt[NN];                         // in-degree (float)
__device__ int   g_gcnt[NB];                        // nodes per graph
__device__ int   g_gptr[NB + 1];                    // CSR over sorted batch
__device__ float g_qstar[NB * 2 * DD];
__device__ float g_hl[NB * DD];
__device__ float g_cl[NB * DD];
__device__ float g_e[NN];                           // attention logits / exp

__device__ __forceinline__ float sigmoidf_(float x) { return 1.f / (1.f + expf(-x)); }

__device__ __forceinline__ uint32_t smem_u32(const void* p) {
    uint32_t a;
    asm("{ .reg .u64 t; cvta.to.shared.u64 t, %1; cvt.u32.u64 %0, t; }" : "=r"(a) : "l"(p));
    return a;
}
__device__ __forceinline__ void ldsm_x4(uint32_t& r0, uint32_t& r1, uint32_t& r2, uint32_t& r3,
                                        uint32_t addr) {
    asm volatile("ldmatrix.sync.aligned.m8n8.x4.shared.b16 {%0, %1, %2, %3}, [%4];"
                 : "=r"(r0), "=r"(r1), "=r"(r2), "=r"(r3) : "r"(addr));
}
__device__ __forceinline__ void mma16816(float* d, const uint32_t* a, const uint32_t* b) {
    asm volatile(
        "mma.sync.aligned.m16n8k16.row.col.f32.bf16.bf16.f32 "
        "{%0, %1, %2, %3}, {%4, %5, %6, %7}, {%8, %9}, {%0, %1, %2, %3};"
        : "+f"(d[0]), "+f"(d[1]), "+f"(d[2]), "+f"(d[3])
        : "r"(a[0]), "r"(a[1]), "r"(a[2]), "r"(a[3]), "r"(b[0]), "r"(b[1]));
}

// copy a [128 rows x 128 bf16] K-major tile into smem with 16B-chunk XOR swizzle
__device__ __forceinline__ void copy_sw(char* dst, const __nv_bfloat16* __restrict__ src) {
    int tid = threadIdx.x;
#pragma unroll
    for (int it = 0; it < 8; it++) {
        int i = tid + it * 256;          // 2048 16B-chunks
        int row = i >> 4;
        int chunk = i & 15;
        uint4 v = *(const uint4*)(src + (size_t)row * 128 + chunk * 8);
        *(uint4*)(dst + row * 256 + ((chunk ^ (row & 7)) << 4)) = v;
    }
}

// ============ W GEMM (HMMA, 1-pass bf16): g_Wb = bf16(h1 @ e2^T + b) ======
// CTA: 128 edges x 4096 N in 32 stripes of 128. 8 warps: 2(M) x 4(N).
// Staged epilogue for coalesced bf16 writes. 2 CTAs/SM (98 KB smem, <=128 regs).
#define STG_STRIDE 272
__global__ __launch_bounds__(256, 2) void k_wgemm_tc(const float* __restrict__ e2b) {
    extern __shared__ char dyn[];
    char* pA = dyn;                  // 32 KB
    char* pB = dyn + 32768;          // 32 KB
    char* pStage = dyn + 65536;      // 128 x 272 B = 34816 B

    int tid = threadIdx.x, wid = tid >> 5, lane = tid & 31;
    int m0 = blockIdx.x * 128;
    int wm = wid & 1;                // warp M: 0..1 (64 rows each)
    int wn = wid >> 1;               // warp N: 0..3 (32 cols each)

    copy_sw(pA, g_h1 + (size_t)m0 * 128);

    int lrow = lane & 7;
    int lsel = lane >> 3;
    int a_row_off = (lsel & 1) * 8 + lrow;
    int a_chunk_sel = lsel >> 1;
    int b_row_off = (lsel >> 1) * 8 + lrow;
    int b_chunk_sel = lsel & 1;

    uint32_t uA = smem_u32(pA), uB = smem_u32(pB);
    int g = lane >> 2, t4 = lane & 3;

    for (int s = 0; s < 32; s++) {
        copy_sw(pB, g_e2 + (size_t)s * 128 * 128);
        __syncthreads();

        float acc[4][4][4];
#pragma unroll
        for (int i = 0; i < 4; i++)
#pragma unroll
            for (int j = 0; j < 4; j++)
#pragma unroll
                for (int q = 0; q < 4; q++) acc[i][j][q] = 0.f;

#pragma unroll
        for (int ks = 0; ks < 8; ks++) {
            int c0 = ks * 2;
            uint32_t afr[4][4];
#pragma unroll
            for (int mt = 0; mt < 4; mt++) {
                int row = wm * 64 + mt * 16 + a_row_off;
                int ch = c0 + a_chunk_sel;
                uint32_t addr = uA + row * 256 + (((ch ^ (row & 7)) & 15) << 4);
                ldsm_x4(afr[mt][0], afr[mt][1], afr[mt][2], afr[mt][3], addr);
            }
            uint32_t bfr[2][4];
#pragma unroll
            for (int bt = 0; bt < 2; bt++) {
                int row = wn * 32 + bt * 16 + b_row_off;
                int ch = c0 + b_chunk_sel;
                uint32_t addr = uB + row * 256 + (((ch ^ (row & 7)) & 15) << 4);
                ldsm_x4(bfr[bt][0], bfr[bt][1], bfr[bt][2], bfr[bt][3], addr);
            }
#pragma unroll
            for (int mt = 0; mt < 4; mt++)
#pragma unroll
                for (int nt = 0; nt < 4; nt++)
                    mma16816(acc[mt][nt], afr[mt], bfr[nt >> 1] + (nt & 1) * 2);
        }

        // staged epilogue: fp32 + bias -> bf16 -> smem -> coalesced GMEM
#pragma unroll
        for (int mt = 0; mt < 4; mt++) {
            int r0 = wm * 64 + mt * 16 + g;
#pragma unroll
            for (int nt = 0; nt < 4; nt++) {
                int col = wn * 32 + nt * 8 + t4 * 2;
                float b0 = e2b[s * 128 + col], b1 = e2b[s * 128 + col + 1];
                __nv_bfloat162 v0 = __floats2bfloat162_rn(acc[mt][nt][0] + b0, acc[mt][nt][1] + b1);
                __nv_bfloat162 v1 = __floats2bfloat162_rn(acc[mt][nt][2] + b0, acc[mt][nt][3] + b1);
                *(__nv_bfloat162*)(pStage + r0 * STG_STRIDE + col * 2) = v0;
                *(__nv_bfloat162*)(pStage + (r0 + 8) * STG_STRIDE + col * 2) = v1;
            }
        }
        __syncthreads();
#pragma unroll
        for (int it = 0; it < 8; it++) {
            int i = tid + it * 256;
            int row = i >> 4, ch = i & 15;
            uint4 v = *(const uint4*)(pStage + row * STG_STRIDE + ch * 16);
            *(uint4*)((char*)(g_Wb + (size_t)(m0 + row) * 4096 + s * 128) + ch * 16) = v;
        }
        __syncthreads();
    }
}

// ---------------- prep: lin0 + zero all state ----------------------------
__global__ void k_prep(const float* __restrict__ x, const float* __restrict__ W,
                       const float* __restrict__ b) {
    int idx = blockIdx.x * blockDim.x + threadIdx.x;
    if (idx < NN * DD) {
        int n = idx >> 6, o = idx & 63;
        const float* xr = x + n * 14;
        const float* wr = W + o * 14;
        float acc = b[o];
#pragma unroll
        for (int i = 0; i < 14; i++) acc += xr[i] * wr[i];
        g_out[idx] = fmaxf(acc, 0.f);
        g_agg[idx] = 0.f;
    }
    if (idx < NN) g_cnt[idx] = 0.f;
    if (idx < NB) g_gcnt[idx] = 0;
    if (idx < NB * 128) g_qstar[idx] = 0.f;
    if (idx < NB * 64) { g_hl[idx] = 0.f; g_cl[idx] = 0.f; }
}

// ---- edge MLP layer 1 (bf16 out) + e2_W cast, in one kernel --------------
#define EP_T1 (NE * 128)
#define EP_T2 (4096 * 128)
__global__ void k_edgeprep(const float* __restrict__ ea, const float* __restrict__ W,
                           const float* __restrict__ b, const float* __restrict__ e2W) {
    int idx = blockIdx.x * blockDim.x + threadIdx.x;
    if (idx < EP_T1) {
        int e = idx >> 7, j = idx & 127;
        const float* er = ea + e * 4;
        const float* wr = W + j * 4;
        float acc = b[j];
#pragma unroll
        for (int i = 0; i < 4; i++) acc += er[i] * wr[i];
        g_h1[idx] = __float2bfloat16(fmaxf(acc, 0.f));
    } else {
        int k = idx - EP_T1;
        if (k < EP_T2) g_e2[k] = __float2bfloat16(e2W[k]);
    }
}

// ---------------- counting ------------------------------------------------
__global__ void k_cnt(const int* __restrict__ ei) {
    int e = blockIdx.x * blockDim.x + threadIdx.x;
    if (e < NE) atomicAdd(&g_cnt[ei[NE + e]], 1.f);
}
__global__ void k_gcnt(const int* __restrict__ batch) {
    int n = blockIdx.x * blockDim.x + threadIdx.x;
    if (n < NN) atomicAdd(&g_gcnt[batch[n]], 1);
}
__global__ void k_scan() {
    __shared__ int s[NB];
    int t = threadIdx.x;
    s[t] = g_gcnt[t];
    __syncthreads();
    for (int off = 1; off < NB; off <<= 1) {
        int v = (t >= off) ? s[t - off] : 0;
        __syncthreads();
        s[t] += v;
        __syncthreads();
    }
    g_gptr[t + 1] = s[t];
    if (t == 0) g_gptr[0] = 0;
}

// ---------------- messages: warp/edge, vectorized bf16 loads -------------
__global__ __launch_bounds__(256) void k_msg(const int* __restrict__ ei) {
    __shared__ float s[8][64];
    int tid = threadIdx.x, w = tid >> 5, l = tid & 31;
    int e0 = blockIdx.x * 8;
#pragma unroll
    for (int i = tid; i < 512; i += 256) {
        int el = i >> 6, c = i & 63;
        s[el][c] = g_out[ei[e0 + el] * 64 + c];
    }
    __syncthreads();
    int e = e0 + w;
    int dst = ei[NE + e];
    int co = (l & 7) * 8;            // col chunk (8 outputs)
    int rb = l >> 3;                 // row group 0..3
    float acc[8];
#pragma unroll
    for (int k = 0; k < 8; k++) acc[k] = 0.f;
    const __nv_bfloat16* Wr = g_Wb + (size_t)e * 4096;
#pragma unroll
    for (int r = 0; r < 16; r++) {
        int row = rb + r * 4;
        uint4 v = *(const uint4*)(Wr + row * 64 + co);
        float si = s[w][row];
        float2 f0 = __bfloat1622float2(*(__nv_bfloat162*)&v.x);
        float2 f1 = __bfloat1622float2(*(__nv_bfloat162*)&v.y);
        float2 f2 = __bfloat1622float2(*(__nv_bfloat162*)&v.z);
        float2 f3 = __bfloat1622float2(*(__nv_bfloat162*)&v.w);
        acc[0] += si * f0.x; acc[1] += si * f0.y;
        acc[2] += si * f1.x; acc[3] += si * f1.y;
        acc[4] += si * f2.x; acc[5] += si * f2.y;
        acc[6] += si * f3.x; acc[7] += si * f3.y;
    }
#pragma unroll
    for (int k = 0; k < 8; k++) {
        acc[k] += __shfl_xor_sync(0xffffffff, acc[k], 8);
        acc[k] += __shfl_xor_sync(0xffffffff, acc[k], 16);
    }
    int sub = l >> 3;                // lane's 2 outputs within the chunk
    atomicAdd(&g_agg[dst * 64 + co + sub * 2], acc[sub * 2]);
    atomicAdd(&g_agg[dst * 64 + co + sub * 2 + 1], acc[sub * 2 + 1]);
}

// ------- m = relu(agg/cnt + out@rootW + conv_b); zero agg for next iter ---
__global__ __launch_bounds__(256) void k_prem(const float* __restrict__ rootW,
                                              const float* __restrict__ convb) {
    __shared__ float sW[4096];
    int tid = threadIdx.x;
    for (int i = tid; i < 4096; i += 256) sW[i] = rootW[i];
    __syncthreads();
    int o = tid & 63, ln = tid >> 6;
    int base = blockIdx.x * 32;
    float cb = convb[o];
    for (int gg = 0; gg < 32; gg += 4) {
        int n = base + gg + ln;
        const float* orow = g_out + n * 64;
        float acc = 0.f;
#pragma unroll
        for (int i = 0; i < 64; i++) acc += orow[i] * sW[i * 64 + o];
        float c = g_cnt[n];
        if (c < 1.f) c = 1.f;
        float v = g_agg[n * 64 + o] / c + acc + cb;
        g_agg[n * 64 + o] = 0.f;     // re-zero for next iteration's atomics
        g_m[n * 64 + o] = fmaxf(v, 0.f);
    }
}

// ---------------- GRU cell over all nodes (16 nodes / block) -------------
__global__ __launch_bounds__(192) void k_gru(const float* __restrict__ Wih,
                                             const float* __restrict__ Whh,
                                             const float* __restrict__ bih,
                                             const float* __restrict__ bhh) {
    __shared__ float sm[16][64], sh[16][64], sgi[16][192], sgh[16][192];
    int tid = threadIdx.x;
    int base = blockIdx.x * 16;
    for (int i = tid; i < 1024; i += 192) {
        int n = i >> 6, c = i & 63;
        sm[n][c] = g_m[(base + n) * 64 + c];
        sh[n][c] = g_out[(base + n) * 64 + c];
    }
    __syncthreads();
    {
        float accI[16], accH[16];
#pragma unroll
        for (int j = 0; j < 16; j++) { accI[j] = 0.f; accH[j] = 0.f; }
        const float* wi = Wih + tid * 64;
        const float* wh = Whh + tid * 64;
        for (int i = 0; i < 64; i++) {
            float a = wi[i], b = wh[i];
#pragma unroll
            for (int j = 0; j < 16; j++) {
                accI[j] += sm[j][i] * a;
                accH[j] += sh[j][i] * b;
            }
        }
        float bi = bih[tid], bh = bhh[tid];
#pragma unroll
        for (int j = 0; j < 16; j++) {
            sgi[j][tid] = accI[j] + bi;
            sgh[j][tid] = accH[j] + bh;
        }
    }
    __syncthreads();
    for (int i = tid; i < 1024; i += 192) {
        int n = i >> 6, c = i & 63;
        float r = sigmoidf_(sgi[n][c] + sgh[n][c]);
        float z = sigmoidf_(sgi[n][64 + c] + sgh[n][64 + c]);
        float nn2 = tanhf(sgi[n][128 + c] + r * sgh[n][128 + c]);
        float hnew = (1.f - z) * nn2 + z * sh[n][c];
        g_out[(base + n) * 64 + c] = hnew;
    }
}

// ---------------- Set2Set LSTM cell (per graph) --------------------------
__global__ __launch_bounds__(256) void k_lstm(const float* __restrict__ Wih,
                                              const float* __restrict__ Whh,
                                              const float* __restrict__ bih,
                                              const float* __restrict__ bhh) {
    int g = blockIdx.x, j = threadIdx.x;
    __shared__ float sq[128], sh[64], sg[256];
    if (j < 128) sq[j] = g_qstar[g * 128 + j];
    else if (j < 192) sh[j - 128] = g_hl[g * 64 + j - 128];
    __syncthreads();
    float acc = bih[j] + bhh[j];
    const float* wi = Wih + j * 128;
#pragma unroll 8
    for (int k = 0; k < 128; k++) acc += sq[k] * wi[k];
    const float* wh = Whh + j * 64;
#pragma unroll 8
    for (int k = 0; k < 64; k++) acc += sh[k] * wh[k];
    sg[j] = acc;
    __syncthreads();
    if (j < 64) {
        float i_ = sg[j], f_ = sg[64 + j], gg = sg[128 + j], o_ = sg[192 + j];
        float c = sigmoidf_(f_) * g_cl[g * 64 + j] + sigmoidf_(i_) * tanhf(gg);
        float h = sigmoidf_(o_) * tanhf(c);
        g_cl[g * 64 + j] = c;
        g_hl[g * 64 + j] = h;
    }
}

// ---------------- Set2Set attention + readout (per graph, contiguous) ----
__global__ __launch_bounds__(64) void k_attn() {
    int g = blockIdx.x, t = threadIdx.x;
    int s = g_gptr[g], e2 = g_gptr[g + 1];
    __shared__ float sq[64], red[64];
    sq[t] = g_hl[g * 64 + t];
    __syncthreads();
    float mx = -3.0e38f;
    for (int n = s + t; n < e2; n += 64) {
        const float* orow = g_out + (size_t)n * 64;
        float acc = 0.f;
#pragma unroll
        for (int i = 0; i < 64; i++) acc += orow[i] * sq[i];
        g_e[n] = acc;
        mx = fmaxf(mx, acc);
    }
    red[t] = mx; __syncthreads();
    for (int st = 32; st > 0; st >>= 1) {
        if (t < st) red[t] = fmaxf(red[t], red[t + st]);
        __syncthreads();
    }
    mx = red[0]; __syncthreads();
    float den = 0.f;
    for (int n = s + t; n < e2; n += 64) {
        float ex = expf(g_e[n] - mx);
        g_e[n] = ex;
        den += ex;
    }
    red[t] = den; __syncthreads();
    for (int st = 32; st > 0; st >>= 1) {
        if (t < st) red[t] += red[t + st];
        __syncthreads();
    }
    den = red[0]; __syncthreads();
    float r = 0.f;
    for (int n = s; n < e2; n++) r += g_e[n] * g_out[(size_t)n * 64 + t];
    if (e2 > s) r /= den;
    g_qstar[g * 128 + t] = sq[t];
    g_qstar[g * 128 + 64 + t] = r;
}

// ---------------- final MLP head -----------------------------------------
__global__ __launch_bounds__(128) void k_final(const float* __restrict__ fc1W,
                                               const float* __restrict__ fc1b,
                                               const float* __restrict__ fc2W,
                                               const float* __restrict__ fc2b,
                                               float* __restrict__ outp) {
    int g = blockIdx.x, j = threadIdx.x;
    __shared__ float sq[128], red[128];
    sq[j] = g_qstar[g * 128 + j];
    __syncthreads();
    float acc = fc1b[j];
    const float* w = fc1W + j * 128;
#pragma unroll 8
    for (int k = 0; k < 128; k++) acc += sq[k] * w[k];
    red[j] = fmaxf(acc, 0.f) * fc2W[j];
    __syncthreads();
    for (int st = 64; st > 0; st >>= 1) {
        if (j < st) red[j] += red[j + st];
        __syncthreads();
    }
    if (j == 0) outp[g] = red[0] + fc2b[0];
}

// ---------------- host: launch sequence ----------------------------------
extern "C" void kernel_launch(void* const* d_in, const int* in_sizes, int n_in,
                              void* d_out, int out_size) {
    const float* x       = (const float*)d_in[0];
    const int*   ei      = (const int*)d_in[1];
    const float* ea      = (const float*)d_in[2];
    const int*   batch   = (const int*)d_in[3];
    const float* lin0_W  = (const float*)d_in[4];
    const float* lin0_b  = (const float*)d_in[5];
    const float* e1_W    = (const float*)d_in[6];
    const float* e1_b    = (const float*)d_in[7];
    const float* e2_W    = (const float*)d_in[8];
    const float* e2_b    = (const float*)d_in[9];
    const float* root_W  = (const float*)d_in[10];
    const float* conv_b  = (const float*)d_in[11];
    const float* gru_Wih = (const float*)d_in[12];
    const float* gru_Whh = (const float*)d_in[13];
    const float* gru_bih = (const float*)d_in[14];
    const float* gru_bhh = (const float*)d_in[15];
    const float* lstm_Wih = (const float*)d_in[16];
    const float* lstm_Whh = (const float*)d_in[17];
    const float* lstm_bih = (const float*)d_in[18];
    const float* lstm_bhh = (const float*)d_in[19];
    const float* fc1_W   = (const float*)d_in[20];
    const float* fc1_b   = (const float*)d_in[21];
    const float* fc2_W   = (const float*)d_in[22];
    const float* fc2_b   = (const float*)d_in[23];
    float* outp = (float*)d_out;

    static bool attr_set = false;
    const int WG_SMEM = 65536 + 128 * STG_STRIDE;    // 100,352 B
    if (!attr_set) {
        cudaFuncSetAttribute(k_wgemm_tc, cudaFuncAttributeMaxDynamicSharedMemorySize, WG_SMEM);
        attr_set = true;
    }

    // 1-3: prep, edgeprep, wgemm; #4 = k_msg (profiled by ncu window)
    k_prep<<<(NN * DD) / 256, 256>>>(x, lin0_W, lin0_b);
    k_edgeprep<<<(EP_T1 + EP_T2) / 256, 256>>>(ea, e1_W, e1_b, e2_W);
    k_wgemm_tc<<<NE / 128, 256, WG_SMEM>>>(e2_b);
    k_msg<<<NE / 8, 256>>>(ei);                  // iteration 1 messages
    k_cnt<<<NE / 256, 256>>>(ei);
    k_gcnt<<<NN / 256, 256>>>(batch);
    k_scan<<<1, NB>>>();
    k_prem<<<NN / 32, 256>>>(root_W, conv_b);
    k_gru<<<NN / 16, 192>>>(gru_Wih, gru_Whh, gru_bih, gru_bhh);

    for (int it = 1; it < 3; it++) {
        k_msg<<<NE / 8, 256>>>(ei);
        k_prem<<<NN / 32, 256>>>(root_W, conv_b);
        k_gru<<<NN / 16, 192>>>(gru_Wih, gru_Whh, gru_bih, gru_bhh);
    }

    for (int st = 0; st < 3; st++) {
        k_lstm<<<NB, 256>>>(lstm_Wih, lstm_Whh, lstm_bih, lstm_bhh);
        k_attn<<<NB, 64>>>();
    }
    k_final<<<NB, 128>>>(fc1_W, fc1_b, fc2_W, fc2_b, outp);
}

// round 7
// speedup vs baseline: 1.4278x; 1.4278x over previous
#include <cuda_runtime.h>
#include <cuda_bf16.h>
#include <math.h>
#include <cstdint>

#define NN 32768
#define NE 49152
#define NB 1024
#define DD 64

// ---------------- device scratch (no allocations allowed) ----------------
__device__ __nv_bfloat16 g_h1[(size_t)NE * 128];    // edge MLP hidden (bf16)
__device__ __nv_bfloat16 g_e2[4096 * 128];          // e2_W (bf16)
__device__ __nv_bfloat16 g_Wb[(size_t)NE * 4096];   // edge weights (bf16, 402 MB)
__device__ float g_out[NN * DD];                    // node features / GRU h
__device__ float g_m[NN * DD];                      // conv output m
__device__ float g_agg[NN * DD];                    // message accumulator
__device__ float g_cnt[NN];                         // in-degree (float)
__device__ int   g_gcnt[NB];                        // nodes per graph
__device__ int   g_gptr[NB + 1];                    // CSR over sorted batch
__device__ float g_qstar[NB * 2 * DD];
__device__ float g_hl[NB * DD];
__device__ float g_cl[NB * DD];
__device__ float g_e[NN];                           // attention logits / exp

__device__ __forceinline__ float sigmoidf_(float x) { return 1.f / (1.f + expf(-x)); }

__device__ __forceinline__ uint32_t smem_u32(const void* p) {
    uint32_t a;
    asm("{ .reg .u64 t; cvta.to.shared.u64 t, %1; cvt.u32.u64 %0, t; }" : "=r"(a) : "l"(p));
    return a;
}
__device__ __forceinline__ void ldsm_x4(uint32_t& r0, uint32_t& r1, uint32_t& r2, uint32_t& r3,
                                        uint32_t addr) {
    asm volatile("ldmatrix.sync.aligned.m8n8.x4.shared.b16 {%0, %1, %2, %3}, [%4];"
                 : "=r"(r0), "=r"(r1), "=r"(r2), "=r"(r3) : "r"(addr));
}
__device__ __forceinline__ void mma16816(float* d, const uint32_t* a, const uint32_t* b) {
    asm volatile(
        "mma.sync.aligned.m16n8k16.row.col.f32.bf16.bf16.f32 "
        "{%0, %1, %2, %3}, {%4, %5, %6, %7}, {%8, %9}, {%0, %1, %2, %3};"
        : "+f"(d[0]), "+f"(d[1]), "+f"(d[2]), "+f"(d[3])
        : "r"(a[0]), "r"(a[1]), "r"(a[2]), "r"(a[3]), "r"(b[0]), "r"(b[1]));
}

// copy a [128 rows x 128 bf16] K-major tile into smem with 16B-chunk XOR swizzle
__device__ __forceinline__ void copy_sw(char* dst, const __nv_bfloat16* __restrict__ src) {
    int tid = threadIdx.x;
#pragma unroll
    for (int it = 0; it < 8; it++) {
        int i = tid + it * 256;          // 2048 16B-chunks
        int row = i >> 4;
        int chunk = i & 15;
        uint4 v = *(const uint4*)(src + (size_t)row * 128 + chunk * 8);
        *(uint4*)(dst + row * 256 + ((chunk ^ (row & 7)) << 4)) = v;
    }
}

// ============ W GEMM (HMMA, 1-pass bf16): g_Wb = bf16(h1 @ e2^T + b) ======
// CTA: 128 edges x 4096 N in 32 stripes of 128. 8 warps: 2(M) x 4(N).
// NOTE: no min-blocks clause — this kernel needs ~255 regs; capping at 128
// (round 6) spilled the 64-float accumulator to local and cost ~2 ms.
#define STG_STRIDE 272
__global__ __launch_bounds__(256) void k_wgemm_tc(const float* __restrict__ e2b) {
    extern __shared__ char dyn[];
    char* pA = dyn;                  // 32 KB
    char* pB = dyn + 32768;          // 32 KB
    char* pStage = dyn + 65536;      // 128 x 272 B = 34816 B

    int tid = threadIdx.x, wid = tid >> 5, lane = tid & 31;
    int m0 = blockIdx.x * 128;
    int wm = wid & 1;                // warp M: 0..1 (64 rows each)
    int wn = wid >> 1;               // warp N: 0..3 (32 cols each)

    copy_sw(pA, g_h1 + (size_t)m0 * 128);

    int lrow = lane & 7;
    int lsel = lane >> 3;
    int a_row_off = (lsel & 1) * 8 + lrow;
    int a_chunk_sel = lsel >> 1;
    int b_row_off = (lsel >> 1) * 8 + lrow;
    int b_chunk_sel = lsel & 1;

    uint32_t uA = smem_u32(pA), uB = smem_u32(pB);
    int g = lane >> 2, t4 = lane & 3;

    for (int s = 0; s < 32; s++) {
        copy_sw(pB, g_e2 + (size_t)s * 128 * 128);
        __syncthreads();

        float acc[4][4][4];
#pragma unroll
        for (int i = 0; i < 4; i++)
#pragma unroll
            for (int j = 0; j < 4; j++)
#pragma unroll
                for (int q = 0; q < 4; q++) acc[i][j][q] = 0.f;

#pragma unroll
        for (int ks = 0; ks < 8; ks++) {
            int c0 = ks * 2;
            uint32_t afr[4][4];
#pragma unroll
            for (int mt = 0; mt < 4; mt++) {
                int row = wm * 64 + mt * 16 + a_row_off;
                int ch = c0 + a_chunk_sel;
                uint32_t addr = uA + row * 256 + (((ch ^ (row & 7)) & 15) << 4);
                ldsm_x4(afr[mt][0], afr[mt][1], afr[mt][2], afr[mt][3], addr);
            }
            uint32_t bfr[2][4];
#pragma unroll
            for (int bt = 0; bt < 2; bt++) {
                int row = wn * 32 + bt * 16 + b_row_off;
                int ch = c0 + b_chunk_sel;
                uint32_t addr = uB + row * 256 + (((ch ^ (row & 7)) & 15) << 4);
                ldsm_x4(bfr[bt][0], bfr[bt][1], bfr[bt][2], bfr[bt][3], addr);
            }
#pragma unroll
            for (int mt = 0; mt < 4; mt++)
#pragma unroll
                for (int nt = 0; nt < 4; nt++)
                    mma16816(acc[mt][nt], afr[mt], bfr[nt >> 1] + (nt & 1) * 2);
        }

        // staged epilogue: fp32 + bias -> bf16 -> smem -> coalesced GMEM
#pragma unroll
        for (int mt = 0; mt < 4; mt++) {
            int r0 = wm * 64 + mt * 16 + g;
#pragma unroll
            for (int nt = 0; nt < 4; nt++) {
                int col = wn * 32 + nt * 8 + t4 * 2;
                float b0 = e2b[s * 128 + col], b1 = e2b[s * 128 + col + 1];
                __nv_bfloat162 v0 = __floats2bfloat162_rn(acc[mt][nt][0] + b0, acc[mt][nt][1] + b1);
                __nv_bfloat162 v1 = __floats2bfloat162_rn(acc[mt][nt][2] + b0, acc[mt][nt][3] + b1);
                *(__nv_bfloat162*)(pStage + r0 * STG_STRIDE + col * 2) = v0;
                *(__nv_bfloat162*)(pStage + (r0 + 8) * STG_STRIDE + col * 2) = v1;
            }
        }
        __syncthreads();
#pragma unroll
        for (int it = 0; it < 8; it++) {
            int i = tid + it * 256;
            int row = i >> 4, ch = i & 15;
            uint4 v = *(const uint4*)(pStage + row * STG_STRIDE + ch * 16);
            *(uint4*)((char*)(g_Wb + (size_t)(m0 + row) * 4096 + s * 128) + ch * 16) = v;
        }
        __syncthreads();
    }
}

// ---------------- prep: lin0 + zero all state ----------------------------
__global__ void k_prep(const float* __restrict__ x, const float* __restrict__ W,
                       const float* __restrict__ b) {
    int idx = blockIdx.x * blockDim.x + threadIdx.x;
    if (idx < NN * DD) {
        int n = idx >> 6, o = idx & 63;
        const float* xr = x + n * 14;
        const float* wr = W + o * 14;
        float acc = b[o];
#pragma unroll
        for (int i = 0; i < 14; i++) acc += xr[i] * wr[i];
        g_out[idx] = fmaxf(acc, 0.f);
        g_agg[idx] = 0.f;
    }
    if (idx < NN) g_cnt[idx] = 0.f;
    if (idx < NB) g_gcnt[idx] = 0;
    if (idx < NB * 128) g_qstar[idx] = 0.f;
    if (idx < NB * 64) { g_hl[idx] = 0.f; g_cl[idx] = 0.f; }
}

// ---- edge MLP layer 1 (bf16 out) + e2_W cast, in one kernel --------------
#define EP_T1 (NE * 128)
#define EP_T2 (4096 * 128)
__global__ void k_edgeprep(const float* __restrict__ ea, const float* __restrict__ W,
                           const float* __restrict__ b, const float* __restrict__ e2W) {
    int idx = blockIdx.x * blockDim.x + threadIdx.x;
    if (idx < EP_T1) {
        int e = idx >> 7, j = idx & 127;
        const float* er = ea + e * 4;
        const float* wr = W + j * 4;
        float acc = b[j];
#pragma unroll
        for (int i = 0; i < 4; i++) acc += er[i] * wr[i];
        g_h1[idx] = __float2bfloat16(fmaxf(acc, 0.f));
    } else {
        int k = idx - EP_T1;
        if (k < EP_T2) g_e2[k] = __float2bfloat16(e2W[k]);
    }
}

// ---------------- counting ------------------------------------------------
__global__ void k_cnt(const int* __restrict__ ei) {
    int e = blockIdx.x * blockDim.x + threadIdx.x;
    if (e < NE) atomicAdd(&g_cnt[ei[NE + e]], 1.f);
}
__global__ void k_gcnt(const int* __restrict__ batch) {
    int n = blockIdx.x * blockDim.x + threadIdx.x;
    if (n < NN) atomicAdd(&g_gcnt[batch[n]], 1);
}
__global__ void k_scan() {
    __shared__ int s[NB];
    int t = threadIdx.x;
    s[t] = g_gcnt[t];
    __syncthreads();
    for (int off = 1; off < NB; off <<= 1) {
        int v = (t >= off) ? s[t - off] : 0;
        __syncthreads();
        s[t] += v;
        __syncthreads();
    }
    g_gptr[t + 1] = s[t];
    if (t == 0) g_gptr[0] = 0;
}

// ---------------- messages: warp/edge, vectorized bf16 loads -------------
__global__ __launch_bounds__(256) void k_msg(const int* __restrict__ ei) {
    __shared__ float s[8][64];
    int tid = threadIdx.x, w = tid >> 5, l = tid & 31;
    int e0 = blockIdx.x * 8;
#pragma unroll
    for (int i = tid; i < 512; i += 256) {
        int el = i >> 6, c = i & 63;
        s[el][c] = g_out[ei[e0 + el] * 64 + c];
    }
    __syncthreads();
    int e = e0 + w;
    int dst = ei[NE + e];
    int co = (l & 7) * 8;            // col chunk (8 outputs)
    int rb = l >> 3;                 // row group 0..3
    float acc[8];
#pragma unroll
    for (int k = 0; k < 8; k++) acc[k] = 0.f;
    const __nv_bfloat16* Wr = g_Wb + (size_t)e * 4096;
#pragma unroll
    for (int r = 0; r < 16; r++) {
        int row = rb + r * 4;
        uint4 v = *(const uint4*)(Wr + row * 64 + co);
        float si = s[w][row];
        float2 f0 = __bfloat1622float2(*(__nv_bfloat162*)&v.x);
        float2 f1 = __bfloat1622float2(*(__nv_bfloat162*)&v.y);
        float2 f2 = __bfloat1622float2(*(__nv_bfloat162*)&v.z);
        float2 f3 = __bfloat1622float2(*(__nv_bfloat162*)&v.w);
        acc[0] += si * f0.x; acc[1] += si * f0.y;
        acc[2] += si * f1.x; acc[3] += si * f1.y;
        acc[4] += si * f2.x; acc[5] += si * f2.y;
        acc[6] += si * f3.x; acc[7] += si * f3.y;
    }
#pragma unroll
    for (int k = 0; k < 8; k++) {
        acc[k] += __shfl_xor_sync(0xffffffff, acc[k], 8);
        acc[k] += __shfl_xor_sync(0xffffffff, acc[k], 16);
    }
    int sub = l >> 3;                // lane's 2 outputs within the chunk
    atomicAdd(&g_agg[dst * 64 + co + sub * 2], acc[sub * 2]);
    atomicAdd(&g_agg[dst * 64 + co + sub * 2 + 1], acc[sub * 2 + 1]);
}

// ------- m = relu(agg/cnt + out@rootW + conv_b); zero agg for next iter ---
__global__ __launch_bounds__(256) void k_prem(const float* __restrict__ rootW,
                                              const float* __restrict__ convb) {
    __shared__ float sW[4096];
    int tid = threadIdx.x;
    for (int i = tid; i < 4096; i += 256) sW[i] = rootW[i];
    __syncthreads();
    int o = tid & 63, ln = tid >> 6;
    int base = blockIdx.x * 32;
    float cb = convb[o];
    for (int gg = 0; gg < 32; gg += 4) {
        int n = base + gg + ln;
        const float* orow = g_out + n * 64;
        float acc = 0.f;
#pragma unroll
        for (int i = 0; i < 64; i++) acc += orow[i] * sW[i * 64 + o];
        float c = g_cnt[n];
        if (c < 1.f) c = 1.f;
        float v = g_agg[n * 64 + o] / c + acc + cb;
        g_agg[n * 64 + o] = 0.f;     // re-zero for next iteration's atomics
        g_m[n * 64 + o] = fmaxf(v, 0.f);
    }
}

// ---------------- GRU cell over all nodes (16 nodes / block) -------------
__global__ __launch_bounds__(192) void k_gru(const float* __restrict__ Wih,
                                             const float* __restrict__ Whh,
                                             const float* __restrict__ bih,
                                             const float* __restrict__ bhh) {
    __shared__ float sm[16][64], sh[16][64], sgi[16][192], sgh[16][192];
    int tid = threadIdx.x;
    int base = blockIdx.x * 16;
    for (int i = tid; i < 1024; i += 192) {
        int n = i >> 6, c = i & 63;
        sm[n][c] = g_m[(base + n) * 64 + c];
        sh[n][c] = g_out[(base + n) * 64 + c];
    }
    __syncthreads();
    {
        float accI[16], accH[16];
#pragma unroll
        for (int j = 0; j < 16; j++) { accI[j] = 0.f; accH[j] = 0.f; }
        const float* wi = Wih + tid * 64;
        const float* wh = Whh + tid * 64;
        for (int i = 0; i < 64; i++) {
            float a = wi[i], b = wh[i];
#pragma unroll
            for (int j = 0; j < 16; j++) {
                accI[j] += sm[j][i] * a;
                accH[j] += sh[j][i] * b;
            }
        }
        float bi = bih[tid], bh = bhh[tid];
#pragma unroll
        for (int j = 0; j < 16; j++) {
            sgi[j][tid] = accI[j] + bi;
            sgh[j][tid] = accH[j] + bh;
        }
    }
    __syncthreads();
    for (int i = tid; i < 1024; i += 192) {
        int n = i >> 6, c = i & 63;
        float r = sigmoidf_(sgi[n][c] + sgh[n][c]);
        float z = sigmoidf_(sgi[n][64 + c] + sgh[n][64 + c]);
        float nn2 = tanhf(sgi[n][128 + c] + r * sgh[n][128 + c]);
        float hnew = (1.f - z) * nn2 + z * sh[n][c];
        g_out[(base + n) * 64 + c] = hnew;
    }
}

// ---------------- Set2Set LSTM cell (per graph) --------------------------
__global__ __launch_bounds__(256) void k_lstm(const float* __restrict__ Wih,
                                              const float* __restrict__ Whh,
                                              const float* __restrict__ bih,
                                              const float* __restrict__ bhh) {
    int g = blockIdx.x, j = threadIdx.x;
    __shared__ float sq[128], sh[64], sg[256];
    if (j < 128) sq[j] = g_qstar[g * 128 + j];
    else if (j < 192) sh[j - 128] = g_hl[g * 64 + j - 128];
    __syncthreads();
    float acc = bih[j] + bhh[j];
    const float* wi = Wih + j * 128;
#pragma unroll 8
    for (int k = 0; k < 128; k++) acc += sq[k] * wi[k];
    const float* wh = Whh + j * 64;
#pragma unroll 8
    for (int k = 0; k < 64; k++) acc += sh[k] * wh[k];
    sg[j] = acc;
    __syncthreads();
    if (j < 64) {
        float i_ = sg[j], f_ = sg[64 + j], gg = sg[128 + j], o_ = sg[192 + j];
        float c = sigmoidf_(f_) * g_cl[g * 64 + j] + sigmoidf_(i_) * tanhf(gg);
        float h = sigmoidf_(o_) * tanhf(c);
        g_cl[g * 64 + j] = c;
        g_hl[g * 64 + j] = h;
    }
}

// ---------------- Set2Set attention + readout (per graph, contiguous) ----
__global__ __launch_bounds__(64) void k_attn() {
    int g = blockIdx.x, t = threadIdx.x;
    int s = g_gptr[g], e2 = g_gptr[g + 1];
    __shared__ float sq[64], red[64];
    sq[t] = g_hl[g * 64 + t];
    __syncthreads();
    float mx = -3.0e38f;
    for (int n = s + t; n < e2; n += 64) {
        const float* orow = g_out + (size_t)n * 64;
        float acc = 0.f;
#pragma unroll
        for (int i = 0; i < 64; i++) acc += orow[i] * sq[i];
        g_e[n] = acc;
        mx = fmaxf(mx, acc);
    }
    red[t] = mx; __syncthreads();
    for (int st = 32; st > 0; st >>= 1) {
        if (t < st) red[t] = fmaxf(red[t], red[t + st]);
        __syncthreads();
    }
    mx = red[0]; __syncthreads();
    float den = 0.f;
    for (int n = s + t; n < e2; n += 64) {
        float ex = expf(g_e[n] - mx);
        g_e[n] = ex;
        den += ex;
    }
    red[t] = den; __syncthreads();
    for (int st = 32; st > 0; st >>= 1) {
        if (t < st) red[t] += red[t + st];
        __syncthreads();
    }
    den = red[0]; __syncthreads();
    float r = 0.f;
    for (int n = s; n < e2; n++) r += g_e[n] * g_out[(size_t)n * 64 + t];
    if (e2 > s) r /= den;
    g_qstar[g * 128 + t] = sq[t];
    g_qstar[g * 128 + 64 + t] = r;
}

// ---------------- final MLP head -----------------------------------------
__global__ __launch_bounds__(128) void k_final(const float* __restrict__ fc1W,
                                               const float* __restrict__ fc1b,
                                               const float* __restrict__ fc2W,
                                               const float* __restrict__ fc2b,
                                               float* __restrict__ outp) {
    int g = blockIdx.x, j = threadIdx.x;
    __shared__ float sq[128], red[128];
    sq[j] = g_qstar[g * 128 + j];
    __syncthreads();
    float acc = fc1b[j];
    const float* w = fc1W + j * 128;
#pragma unroll 8
    for (int k = 0; k < 128; k++) acc += sq[k] * w[k];
    red[j] = fmaxf(acc, 0.f) * fc2W[j];
    __syncthreads();
    for (int st = 64; st > 0; st >>= 1) {
        if (j < st) red[j] += red[j + st];
        __syncthreads();
    }
    if (j == 0) outp[g] = red[0] + fc2b[0];
}

// ---------------- host: launch sequence ----------------------------------
extern "C" void kernel_launch(void* const* d_in, const int* in_sizes, int n_in,
                              void* d_out, int out_size) {
    const float* x       = (const float*)d_in[0];
    const int*   ei      = (const int*)d_in[1];
    const float* ea      = (const float*)d_in[2];
    const int*   batch   = (const int*)d_in[3];
    const float* lin0_W  = (const float*)d_in[4];
    const float* lin0_b  = (const float*)d_in[5];
    const float* e1_W    = (const float*)d_in[6];
    const float* e1_b    = (const float*)d_in[7];
    const float* e2_W    = (const float*)d_in[8];
    const float* e2_b    = (const float*)d_in[9];
    const float* root_W  = (const float*)d_in[10];
    const float* conv_b  = (const float*)d_in[11];
    const float* gru_Wih = (const float*)d_in[12];
    const float* gru_Whh = (const float*)d_in[13];
    const float* gru_bih = (const float*)d_in[14];
    const float* gru_bhh = (const float*)d_in[15];
    const float* lstm_Wih = (const float*)d_in[16];
    const float* lstm_Whh = (const float*)d_in[17];
    const float* lstm_bih = (const float*)d_in[18];
    const float* lstm_bhh = (const float*)d_in[19];
    const float* fc1_W   = (const float*)d_in[20];
    const float* fc1_b   = (const float*)d_in[21];
    const float* fc2_W   = (const float*)d_in[22];
    const float* fc2_b   = (const float*)d_in[23];
    float* outp = (float*)d_out;

    static bool attr_set = false;
    const int WG_SMEM = 65536 + 128 * STG_STRIDE;    // 100,352 B
    if (!attr_set) {
        cudaFuncSetAttribute(k_wgemm_tc, cudaFuncAttributeMaxDynamicSharedMemorySize, WG_SMEM);
        attr_set = true;
    }

    // k_wgemm_tc in slot #4 — the launch position ncu's window captures.
    k_prep<<<(NN * DD) / 256, 256>>>(x, lin0_W, lin0_b);
    k_edgeprep<<<(EP_T1 + EP_T2) / 256, 256>>>(ea, e1_W, e1_b, e2_W);
    k_cnt<<<NE / 256, 256>>>(ei);
    k_wgemm_tc<<<NE / 128, 256, WG_SMEM>>>(e2_b);
    k_gcnt<<<NN / 256, 256>>>(batch);
    k_scan<<<1, NB>>>();

    for (int it = 0; it < 3; it++) {
        k_msg<<<NE / 8, 256>>>(ei);
        k_prem<<<NN / 32, 256>>>(root_W, conv_b);
        k_gru<<<NN / 16, 192>>>(gru_Wih, gru_Whh, gru_bih, gru_bhh);
    }

    for (int st = 0; st < 3; st++) {
        k_lstm<<<NB, 256>>>(lstm_Wih, lstm_Whh, lstm_bih, lstm_bhh);
        k_attn<<<NB, 64>>>();
    }
    k_final<<<NB, 128>>>(fc1_W, fc1_b, fc2_W, fc2_b, outp);
}

// round 8
// speedup vs baseline: 2.6369x; 1.8468x over previous
#include <cuda_runtime.h>
#include <cuda_bf16.h>
#include <math.h>
#include <cstdint>

#define NN 32768
#define NE 49152
#define NB 1024
#define DD 64

// ---------------- device scratch (no allocations allowed) ----------------
__device__ __nv_bfloat16 g_h1[(size_t)NE * 128];    // edge MLP hidden (bf16)
__device__ __nv_bfloat16 g_e2[4096 * 128];          // e2_W (bf16)
__device__ __nv_bfloat16 g_Wb[(size_t)NE * 4096];   // edge weights (bf16, 402 MB)
__device__ float g_out[NN * DD];                    // node features / GRU h
__device__ float g_m[NN * DD];                      // conv output m
__device__ float g_agg[NN * DD];                    // message accumulator
__device__ float g_cnt[NN];                         // in-degree (float)
__device__ int   g_gcnt[NB];                        // nodes per graph
__device__ int   g_gptr[NB + 1];                    // CSR over sorted batch
__device__ float g_qstar[NB * 2 * DD];
__device__ float g_hl[NB * DD];
__device__ float g_cl[NB * DD];
__device__ float g_e[NN];                           // attention logits / exp

__device__ __forceinline__ float sigmoidf_(float x) { return 1.f / (1.f + expf(-x)); }

__device__ __forceinline__ uint32_t smem_u32(const void* p) {
    uint32_t a;
    asm("{ .reg .u64 t; cvta.to.shared.u64 t, %1; cvt.u32.u64 %0, t; }" : "=r"(a) : "l"(p));
    return a;
}
__device__ __forceinline__ void ldsm_x4(uint32_t& r0, uint32_t& r1, uint32_t& r2, uint32_t& r3,
                                        uint32_t addr) {
    asm volatile("ldmatrix.sync.aligned.m8n8.x4.shared.b16 {%0, %1, %2, %3}, [%4];"
                 : "=r"(r0), "=r"(r1), "=r"(r2), "=r"(r3) : "r"(addr));
}
__device__ __forceinline__ void mma16816(float* d, const uint32_t* a, const uint32_t* b) {
    asm volatile(
        "mma.sync.aligned.m16n8k16.row.col.f32.bf16.bf16.f32 "
        "{%0, %1, %2, %3}, {%4, %5, %6, %7}, {%8, %9}, {%0, %1, %2, %3};"
        : "+f"(d[0]), "+f"(d[1]), "+f"(d[2]), "+f"(d[3])
        : "r"(a[0]), "r"(a[1]), "r"(a[2]), "r"(a[3]), "r"(b[0]), "r"(b[1]));
}

// copy a [128 rows x 128 bf16] K-major tile into smem with 16B-chunk XOR swizzle
__device__ __forceinline__ void copy_sw(char* dst, const __nv_bfloat16* __restrict__ src) {
    int tid = threadIdx.x;
#pragma unroll
    for (int it = 0; it < 8; it++) {
        int i = tid + it * 256;          // 2048 16B-chunks
        int row = i >> 4;
        int chunk = i & 15;
        uint4 v = *(const uint4*)(src + (size_t)row * 128 + chunk * 8);
        *(uint4*)(dst + row * 256 + ((chunk ^ (row & 7)) << 4)) = v;
    }
}
// same, but via cp.async (16B, L2-bypass-L1 .cg path)
__device__ __forceinline__ void copy_sw_async(uint32_t dst, const __nv_bfloat16* __restrict__ src) {
    int tid = threadIdx.x;
#pragma unroll
    for (int it = 0; it < 8; it++) {
        int i = tid + it * 256;
        int row = i >> 4;
        int chunk = i & 15;
        uint32_t d = dst + row * 256 + ((chunk ^ (row & 7)) << 4);
        asm volatile("cp.async.cg.shared.global [%0], [%1], 16;"
                     :: "r"(d), "l"(src + (size_t)row * 128 + chunk * 8));
    }
}
#define CP_COMMIT() asm volatile("cp.async.commit_group;" ::: "memory")
#define CP_WAIT0()  asm volatile("cp.async.wait_group 0;" ::: "memory")

// ============ W GEMM (HMMA, 1-pass bf16): g_Wb = bf16(h1 @ e2^T + b) ======
// CTA: 128 edges x 4096 N in 32 stripes of 128. 8 warps: 2(M) x 4(N).
// B stripes double-buffered via cp.async; prefetch overlaps MMA + epilogue.
// NOTE: no min-blocks clause — needs ~162 regs; capping at 128 spills.
#define STG_STRIDE 272
__global__ __launch_bounds__(256) void k_wgemm_tc(const float* __restrict__ e2b) {
    extern __shared__ char dyn[];
    char* pA = dyn;                  // 32 KB
    char* pB0 = dyn + 32768;         // 32 KB
    char* pB1 = dyn + 65536;         // 32 KB
    char* pStage = dyn + 98304;      // 128 x 272 B = 34816 B

    int tid = threadIdx.x, wid = tid >> 5, lane = tid & 31;
    int m0 = blockIdx.x * 128;
    int wm = wid & 1;                // warp M: 0..1 (64 rows each)
    int wn = wid >> 1;               // warp N: 0..3 (32 cols each)

    uint32_t uA = smem_u32(pA);
    uint32_t uB[2] = {smem_u32(pB0), smem_u32(pB1)};

    // prefetch B stripe 0, load A with regular stores
    copy_sw_async(uB[0], g_e2);
    CP_COMMIT();
    copy_sw(pA, g_h1 + (size_t)m0 * 128);

    int lrow = lane & 7;
    int lsel = lane >> 3;
    int a_row_off = (lsel & 1) * 8 + lrow;
    int a_chunk_sel = lsel >> 1;
    int b_row_off = (lsel >> 1) * 8 + lrow;
    int b_chunk_sel = lsel & 1;
    int g = lane >> 2, t4 = lane & 3;

    for (int s = 0; s < 32; s++) {
        CP_WAIT0();
        __syncthreads();             // B[s] visible to all; pStage drained
        if (s + 1 < 32) {
            copy_sw_async(uB[(s + 1) & 1], g_e2 + (size_t)(s + 1) * 128 * 128);
            CP_COMMIT();
        }
        uint32_t uBc = uB[s & 1];

        float acc[4][4][4];
#pragma unroll
        for (int i = 0; i < 4; i++)
#pragma unroll
            for (int j = 0; j < 4; j++)
#pragma unroll
                for (int q = 0; q < 4; q++) acc[i][j][q] = 0.f;

#pragma unroll
        for (int ks = 0; ks < 8; ks++) {
            int c0 = ks * 2;
            uint32_t afr[4][4];
#pragma unroll
            for (int mt = 0; mt < 4; mt++) {
                int row = wm * 64 + mt * 16 + a_row_off;
                int ch = c0 + a_chunk_sel;
                uint32_t addr = uA + row * 256 + (((ch ^ (row & 7)) & 15) << 4);
                ldsm_x4(afr[mt][0], afr[mt][1], afr[mt][2], afr[mt][3], addr);
            }
            uint32_t bfr[2][4];
#pragma unroll
            for (int bt = 0; bt < 2; bt++) {
                int row = wn * 32 + bt * 16 + b_row_off;
                int ch = c0 + b_chunk_sel;
                uint32_t addr = uBc + row * 256 + (((ch ^ (row & 7)) & 15) << 4);
                ldsm_x4(bfr[bt][0], bfr[bt][1], bfr[bt][2], bfr[bt][3], addr);
            }
#pragma unroll
            for (int mt = 0; mt < 4; mt++)
#pragma unroll
                for (int nt = 0; nt < 4; nt++)
                    mma16816(acc[mt][nt], afr[mt], bfr[nt >> 1] + (nt & 1) * 2);
        }

        // staged epilogue: fp32 + bias -> bf16 -> smem -> coalesced GMEM
#pragma unroll
        for (int mt = 0; mt < 4; mt++) {
            int r0 = wm * 64 + mt * 16 + g;
#pragma unroll
            for (int nt = 0; nt < 4; nt++) {
                int col = wn * 32 + nt * 8 + t4 * 2;
                float b0 = e2b[s * 128 + col], b1 = e2b[s * 128 + col + 1];
                __nv_bfloat162 v0 = __floats2bfloat162_rn(acc[mt][nt][0] + b0, acc[mt][nt][1] + b1);
                __nv_bfloat162 v1 = __floats2bfloat162_rn(acc[mt][nt][2] + b0, acc[mt][nt][3] + b1);
                *(__nv_bfloat162*)(pStage + r0 * STG_STRIDE + col * 2) = v0;
                *(__nv_bfloat162*)(pStage + (r0 + 8) * STG_STRIDE + col * 2) = v1;
            }
        }
        __syncthreads();
#pragma unroll
        for (int it = 0; it < 8; it++) {
            int i = tid + it * 256;
            int row = i >> 4, ch = i & 15;
            uint4 v = *(const uint4*)(pStage + row * STG_STRIDE + ch * 16);
            *(uint4*)((char*)(g_Wb + (size_t)(m0 + row) * 4096 + s * 128) + ch * 16) = v;
        }
    }
}

// ---------------- prep: lin0 + zero all state ----------------------------
__global__ void k_prep(const float* __restrict__ x, const float* __restrict__ W,
                       const float* __restrict__ b) {
    int idx = blockIdx.x * blockDim.x + threadIdx.x;
    if (idx < NN * DD) {
        int n = idx >> 6, o = idx & 63;
        const float* xr = x + n * 14;
        const float* wr = W + o * 14;
        float acc = b[o];
#pragma unroll
        for (int i = 0; i < 14; i++) acc += xr[i] * wr[i];
        g_out[idx] = fmaxf(acc, 0.f);
        g_agg[idx] = 0.f;
    }
    if (idx < NN) g_cnt[idx] = 0.f;
    if (idx < NB) g_gcnt[idx] = 0;
    if (idx < NB * 128) g_qstar[idx] = 0.f;
    if (idx < NB * 64) { g_hl[idx] = 0.f; g_cl[idx] = 0.f; }
}

// ---- edge MLP layer 1 (bf16 out) + e2_W cast, in one kernel --------------
#define EP_T1 (NE * 128)
#define EP_T2 (4096 * 128)
__global__ void k_edgeprep(const float* __restrict__ ea, const float* __restrict__ W,
                           const float* __restrict__ b, const float* __restrict__ e2W) {
    int idx = blockIdx.x * blockDim.x + threadIdx.x;
    if (idx < EP_T1) {
        int e = idx >> 7, j = idx & 127;
        const float* er = ea + e * 4;
        const float* wr = W + j * 4;
        float acc = b[j];
#pragma unroll
        for (int i = 0; i < 4; i++) acc += er[i] * wr[i];
        g_h1[idx] = __float2bfloat16(fmaxf(acc, 0.f));
    } else {
        int k = idx - EP_T1;
        if (k < EP_T2) g_e2[k] = __float2bfloat16(e2W[k]);
    }
}

// ---------------- counting ------------------------------------------------
__global__ void k_cnt(const int* __restrict__ ei) {
    int e = blockIdx.x * blockDim.x + threadIdx.x;
    if (e < NE) atomicAdd(&g_cnt[ei[NE + e]], 1.f);
}
__global__ void k_gcnt(const int* __restrict__ batch) {
    int n = blockIdx.x * blockDim.x + threadIdx.x;
    if (n < NN) atomicAdd(&g_gcnt[batch[n]], 1);
}
__global__ void k_scan() {
    __shared__ int s[NB];
    int t = threadIdx.x;
    s[t] = g_gcnt[t];
    __syncthreads();
    for (int off = 1; off < NB; off <<= 1) {
        int v = (t >= off) ? s[t - off] : 0;
        __syncthreads();
        s[t] += v;
        __syncthreads();
    }
    g_gptr[t + 1] = s[t];
    if (t == 0) g_gptr[0] = 0;
}

// ---------------- messages: warp/edge, vectorized bf16 loads -------------
__global__ __launch_bounds__(256) void k_msg(const int* __restrict__ ei) {
    __shared__ float s[8][64];
    int tid = threadIdx.x, w = tid >> 5, l = tid & 31;
    int e0 = blockIdx.x * 8;
#pragma unroll
    for (int i = tid; i < 512; i += 256) {
        int el = i >> 6, c = i & 63;
        s[el][c] = g_out[ei[e0 + el] * 64 + c];
    }
    __syncthreads();
    int e = e0 + w;
    int dst = ei[NE + e];
    int co = (l & 7) * 8;            // col chunk (8 outputs)
    int rb = l >> 3;                 // row group 0..3
    float acc[8];
#pragma unroll
    for (int k = 0; k < 8; k++) acc[k] = 0.f;
    const __nv_bfloat16* Wr = g_Wb + (size_t)e * 4096;
#pragma unroll
    for (int r = 0; r < 16; r++) {
        int row = rb + r * 4;
        uint4 v = *(const uint4*)(Wr + row * 64 + co);
        float si = s[w][row];
        float2 f0 = __bfloat1622float2(*(__nv_bfloat162*)&v.x);
        float2 f1 = __bfloat1622float2(*(__nv_bfloat162*)&v.y);
        float2 f2 = __bfloat1622float2(*(__nv_bfloat162*)&v.z);
        float2 f3 = __bfloat1622float2(*(__nv_bfloat162*)&v.w);
        acc[0] += si * f0.x; acc[1] += si * f0.y;
        acc[2] += si * f1.x; acc[3] += si * f1.y;
        acc[4] += si * f2.x; acc[5] += si * f2.y;
        acc[6] += si * f3.x; acc[7] += si * f3.y;
    }
#pragma unroll
    for (int k = 0; k < 8; k++) {
        acc[k] += __shfl_xor_sync(0xffffffff, acc[k], 8);
        acc[k] += __shfl_xor_sync(0xffffffff, acc[k], 16);
    }
    int sub = l >> 3;                // lane's 2 outputs within the chunk
    atomicAdd(&g_agg[dst * 64 + co + sub * 2], acc[sub * 2]);
    atomicAdd(&g_agg[dst * 64 + co + sub * 2 + 1], acc[sub * 2 + 1]);
}

// ------- m = relu(agg/cnt + out@rootW + conv_b); zero agg for next iter ---
__global__ __launch_bounds__(256) void k_prem(const float* __restrict__ rootW,
                                              const float* __restrict__ convb) {
    __shared__ float sW[4096];
    int tid = threadIdx.x;
    for (int i = tid; i < 4096; i += 256) sW[i] = rootW[i];
    __syncthreads();
    int o = tid & 63, ln = tid >> 6;
    int base = blockIdx.x * 32;
    float cb = convb[o];
    for (int gg = 0; gg < 32; gg += 4) {
        int n = base + gg + ln;
        const float* orow = g_out + n * 64;
        float acc = 0.f;
#pragma unroll
        for (int i = 0; i < 64; i++) acc += orow[i] * sW[i * 64 + o];
        float c = g_cnt[n];
        if (c < 1.f) c = 1.f;
        float v = g_agg[n * 64 + o] / c + acc + cb;
        g_agg[n * 64 + o] = 0.f;     // re-zero for next iteration's atomics
        g_m[n * 64 + o] = fmaxf(v, 0.f);
    }
}

// ---------------- GRU cell over all nodes (16 nodes / block) -------------
// Weight rows loaded as float4 (4x fewer L1tex wavefronts than scalar).
__global__ __launch_bounds__(192) void k_gru(const float* __restrict__ Wih,
                                             const float* __restrict__ Whh,
                                             const float* __restrict__ bih,
                                             const float* __restrict__ bhh) {
    __shared__ float sm[16][64], sh[16][64], sgi[16][192], sgh[16][192];
    int tid = threadIdx.x;
    int base = blockIdx.x * 16;
    for (int i = tid; i < 1024; i += 192) {
        int n = i >> 6, c = i & 63;
        sm[n][c] = g_m[(base + n) * 64 + c];
        sh[n][c] = g_out[(base + n) * 64 + c];
    }
    __syncthreads();
    {
        float accI[16], accH[16];
#pragma unroll
        for (int j = 0; j < 16; j++) { accI[j] = 0.f; accH[j] = 0.f; }
        const float4* wi4 = (const float4*)(Wih + tid * 64);
        const float4* wh4 = (const float4*)(Whh + tid * 64);
#pragma unroll
        for (int i4 = 0; i4 < 16; i4++) {
            float4 a = wi4[i4];
            float4 b = wh4[i4];
            int i = i4 * 4;
#pragma unroll
            for (int j = 0; j < 16; j++) {
                accI[j] += sm[j][i] * a.x + sm[j][i + 1] * a.y
                         + sm[j][i + 2] * a.z + sm[j][i + 3] * a.w;
                accH[j] += sh[j][i] * b.x + sh[j][i + 1] * b.y
                         + sh[j][i + 2] * b.z + sh[j][i + 3] * b.w;
            }
        }
        float bi = bih[tid], bh = bhh[tid];
#pragma unroll
        for (int j = 0; j < 16; j++) {
            sgi[j][tid] = accI[j] + bi;
            sgh[j][tid] = accH[j] + bh;
        }
    }
    __syncthreads();
    for (int i = tid; i < 1024; i += 192) {
        int n = i >> 6, c = i & 63;
        float r = sigmoidf_(sgi[n][c] + sgh[n][c]);
        float z = sigmoidf_(sgi[n][64 + c] + sgh[n][64 + c]);
        float nn2 = tanhf(sgi[n][128 + c] + r * sgh[n][128 + c]);
        float hnew = (1.f - z) * nn2 + z * sh[n][c];
        g_out[(base + n) * 64 + c] = hnew;
    }
}

// ---------------- Set2Set LSTM cell (per graph) --------------------------
__global__ __launch_bounds__(256) void k_lstm(const float* __restrict__ Wih,
                                              const float* __restrict__ Whh,
                                              const float* __restrict__ bih,
                                              const float* __restrict__ bhh) {
    int g = blockIdx.x, j = threadIdx.x;
    __shared__ float sq[128], sh[64], sg[256];
    if (j < 128) sq[j] = g_qstar[g * 128 + j];
    else if (j < 192) sh[j - 128] = g_hl[g * 64 + j - 128];
    __syncthreads();
    float acc = bih[j] + bhh[j];
    const float4* wi4 = (const float4*)(Wih + j * 128);
#pragma unroll
    for (int k4 = 0; k4 < 32; k4++) {
        float4 v = wi4[k4];
        int k = k4 * 4;
        acc += sq[k] * v.x + sq[k + 1] * v.y + sq[k + 2] * v.z + sq[k + 3] * v.w;
    }
    const float4* wh4 = (const float4*)(Whh + j * 64);
#pragma unroll
    for (int k4 = 0; k4 < 16; k4++) {
        float4 v = wh4[k4];
        int k = k4 * 4;
        acc += sh[k] * v.x + sh[k + 1] * v.y + sh[k + 2] * v.z + sh[k + 3] * v.w;
    }
    sg[j] = acc;
    __syncthreads();
    if (j < 64) {
        float i_ = sg[j], f_ = sg[64 + j], gg = sg[128 + j], o_ = sg[192 + j];
        float c = sigmoidf_(f_) * g_cl[g * 64 + j] + sigmoidf_(i_) * tanhf(gg);
        float h = sigmoidf_(o_) * tanhf(c);
        g_cl[g * 64 + j] = c;
        g_hl[g * 64 + j] = h;
    }
}

// ---------------- Set2Set attention + readout (per graph, contiguous) ----
__global__ __launch_bounds__(64) void k_attn() {
    int g = blockIdx.x, t = threadIdx.x;
    int s = g_gptr[g], e2 = g_gptr[g + 1];
    __shared__ float sq[64], red[64];
    sq[t] = g_hl[g * 64 + t];
    __syncthreads();
    float mx = -3.0e38f;
    for (int n = s + t; n < e2; n += 64) {
        const float* orow = g_out + (size_t)n * 64;
        float acc = 0.f;
#pragma unroll
        for (int i = 0; i < 64; i++) acc += orow[i] * sq[i];
        g_e[n] = acc;
        mx = fmaxf(mx, acc);
    }
    red[t] = mx; __syncthreads();
    for (int st = 32; st > 0; st >>= 1) {
        if (t < st) red[t] = fmaxf(red[t], red[t + st]);
        __syncthreads();
    }
    mx = red[0]; __syncthreads();
    float den = 0.f;
    for (int n = s + t; n < e2; n += 64) {
        float ex = expf(g_e[n] - mx);
        g_e[n] = ex;
        den += ex;
    }
    red[t] = den; __syncthreads();
    for (int st = 32; st > 0; st >>= 1) {
        if (t < st) red[t] += red[t + st];
        __syncthreads();
    }
    den = red[0]; __syncthreads();
    float r = 0.f;
    for (int n = s; n < e2; n++) r += g_e[n] * g_out[(size_t)n * 64 + t];
    if (e2 > s) r /= den;
    g_qstar[g * 128 + t] = sq[t];
    g_qstar[g * 128 + 64 + t] = r;
}

// ---------------- final MLP head -----------------------------------------
__global__ __launch_bounds__(128) void k_final(const float* __restrict__ fc1W,
                                               const float* __restrict__ fc1b,
                                               const float* __restrict__ fc2W,
                                               const float* __restrict__ fc2b,
                                               float* __restrict__ outp) {
    int g = blockIdx.x, j = threadIdx.x;
    __shared__ float sq[128], red[128];
    sq[j] = g_qstar[g * 128 + j];
    __syncthreads();
    float acc = fc1b[j];
    const float4* w4 = (const float4*)(fc1W + j * 128);
#pragma unroll
    for (int k4 = 0; k4 < 32; k4++) {
        float4 v = w4[k4];
        int k = k4 * 4;
        acc += sq[k] * v.x + sq[k + 1] * v.y + sq[k + 2] * v.z + sq[k + 3] * v.w;
    }
    red[j] = fmaxf(acc, 0.f) * fc2W[j];
    __syncthreads();
    for (int st = 64; st > 0; st >>= 1) {
        if (j < st) red[j] += red[j + st];
        __syncthreads();
    }
    if (j == 0) outp[g] = red[0] + fc2b[0];
}

// ---------------- host: launch sequence ----------------------------------
extern "C" void kernel_launch(void* const* d_in, const int* in_sizes, int n_in,
                              void* d_out, int out_size) {
    const float* x       = (const float*)d_in[0];
    const int*   ei      = (const int*)d_in[1];
    const float* ea      = (const float*)d_in[2];
    const int*   batch   = (const int*)d_in[3];
    const float* lin0_W  = (const float*)d_in[4];
    const float* lin0_b  = (const float*)d_in[5];
    const float* e1_W    = (const float*)d_in[6];
    const float* e1_b    = (const float*)d_in[7];
    const float* e2_W    = (const float*)d_in[8];
    const float* e2_b    = (const float*)d_in[9];
    const float* root_W  = (const float*)d_in[10];
    const float* conv_b  = (const float*)d_in[11];
    const float* gru_Wih = (const float*)d_in[12];
    const float* gru_Whh = (const float*)d_in[13];
    const float* gru_bih = (const float*)d_in[14];
    const float* gru_bhh = (const float*)d_in[15];
    const float* lstm_Wih = (const float*)d_in[16];
    const float* lstm_Whh = (const float*)d_in[17];
    const float* lstm_bih = (const float*)d_in[18];
    const float* lstm_bhh = (const float*)d_in[19];
    const float* fc1_W   = (const float*)d_in[20];
    const float* fc1_b   = (const float*)d_in[21];
    const float* fc2_W   = (const float*)d_in[22];
    const float* fc2_b   = (const float*)d_in[23];
    float* outp = (float*)d_out;

    static bool attr_set = false;
    const int WG_SMEM = 98304 + 128 * STG_STRIDE;    // 133,120 B
    if (!attr_set) {
        cudaFuncSetAttribute(k_wgemm_tc, cudaFuncAttributeMaxDynamicSharedMemorySize, WG_SMEM);
        attr_set = true;
    }

    // k_wgemm_tc in slot #4 — the launch position ncu's window captures.
    k_prep<<<(NN * DD) / 256, 256>>>(x, lin0_W, lin0_b);
    k_edgeprep<<<(EP_T1 + EP_T2) / 256, 256>>>(ea, e1_W, e1_b, e2_W);
    k_cnt<<<NE / 256, 256>>>(ei);
    k_wgemm_tc<<<NE / 128, 256, WG_SMEM>>>(e2_b);
    k_gcnt<<<NN / 256, 256>>>(batch);
    k_scan<<<1, NB>>>();

    for (int it = 0; it < 3; it++) {
        k_msg<<<NE / 8, 256>>>(ei);
        k_prem<<<NN / 32, 256>>>(root_W, conv_b);
        k_gru<<<NN / 16, 192>>>(gru_Wih, gru_Whh, gru_bih, gru_bhh);
    }

    for (int st = 0; st < 3; st++) {
        k_lstm<<<NB, 256>>>(lstm_Wih, lstm_Whh, lstm_bih, lstm_bhh);
        k_attn<<<NB, 64>>>();
    }
    k_final<<<NB, 128>>>(fc1_W, fc1_b, fc2_W, fc2_b, outp);
}

// round 9
// speedup vs baseline: 3.2393x; 1.2284x over previous
#include <cuda_runtime.h>
#include <cuda_bf16.h>
#include <math.h>
#include <cstdint>

#define NN 32768
#define NE 49152
#define NB 1024
#define DD 64

// ---------------- device scratch (no allocations allowed) ----------------
__device__ __nv_bfloat16 g_h1[(size_t)NE * 128];    // edge MLP hidden (bf16)
__device__ __nv_bfloat16 g_e2[4096 * 128];          // e2_W (bf16)
__device__ __nv_bfloat16 g_Wb[(size_t)NE * 4096];   // edge weights (bf16, 402 MB)
__device__ float g_out[NN * DD];                    // node features / GRU h
__device__ float g_m[NN * DD];                      // conv output m
__device__ float g_agg[NN * DD];                    // message accumulator
__device__ float g_cnt[NN];                         // in-degree (float)
__device__ int   g_gcnt[NB];                        // nodes per graph
__device__ int   g_gptr[NB + 1];                    // CSR over sorted batch
// transposed small weights (coalesced lane-consecutive access)
__device__ float g_gWihT[64 * 192];                 // gru Wih^T  [i][gate]
__device__ float g_gWhhT[64 * 192];                 // gru Whh^T
__device__ float g_lWihT[128 * 256];                // lstm Wih^T [k][gate]
__device__ float g_lWhhT[64 * 256];                 // lstm Whh^T
__device__ float g_fc1T[128 * 128];                 // fc1^T      [k][gate]

__device__ __forceinline__ float sigmoidf_(float x) { return 1.f / (1.f + expf(-x)); }

__device__ __forceinline__ uint32_t smem_u32(const void* p) {
    uint32_t a;
    asm("{ .reg .u64 t; cvta.to.shared.u64 t, %1; cvt.u32.u64 %0, t; }" : "=r"(a) : "l"(p));
    return a;
}
__device__ __forceinline__ void ldsm_x4(uint32_t& r0, uint32_t& r1, uint32_t& r2, uint32_t& r3,
                                        uint32_t addr) {
    asm volatile("ldmatrix.sync.aligned.m8n8.x4.shared.b16 {%0, %1, %2, %3}, [%4];"
                 : "=r"(r0), "=r"(r1), "=r"(r2), "=r"(r3) : "r"(addr));
}
__device__ __forceinline__ void mma16816(float* d, const uint32_t* a, const uint32_t* b) {
    asm volatile(
        "mma.sync.aligned.m16n8k16.row.col.f32.bf16.bf16.f32 "
        "{%0, %1, %2, %3}, {%4, %5, %6, %7}, {%8, %9}, {%0, %1, %2, %3};"
        : "+f"(d[0]), "+f"(d[1]), "+f"(d[2]), "+f"(d[3])
        : "r"(a[0]), "r"(a[1]), "r"(a[2]), "r"(a[3]), "r"(b[0]), "r"(b[1]));
}

// copy a [128 x 128 bf16] tile into smem with 16B-chunk XOR swizzle (512 thr)
__device__ __forceinline__ void copy_sw512(char* dst, const __nv_bfloat16* __restrict__ src) {
    int tid = threadIdx.x;
#pragma unroll
    for (int it = 0; it < 4; it++) {
        int i = tid + it * 512;          // 2048 16B-chunks
        int row = i >> 4;
        int chunk = i & 15;
        uint4 v = *(const uint4*)(src + (size_t)row * 128 + chunk * 8);
        *(uint4*)(dst + row * 256 + ((chunk ^ (row & 7)) << 4)) = v;
    }
}
__device__ __forceinline__ void copy_sw512_async(uint32_t dst, const __nv_bfloat16* __restrict__ src) {
    int tid = threadIdx.x;
#pragma unroll
    for (int it = 0; it < 4; it++) {
        int i = tid + it * 512;
        int row = i >> 4;
        int chunk = i & 15;
        uint32_t d = dst + row * 256 + ((chunk ^ (row & 7)) << 4);
        asm volatile("cp.async.cg.shared.global [%0], [%1], 16;"
                     :: "r"(d), "l"(src + (size_t)row * 128 + chunk * 8));
    }
}
#define CP_COMMIT() asm volatile("cp.async.commit_group;" ::: "memory")
#define CP_WAIT0()  asm volatile("cp.async.wait_group 0;" ::: "memory")

// ============ W GEMM (HMMA, 1-pass bf16): g_Wb = bf16(h1 @ e2^T + b) ======
// 512 threads (16 warps: 4 M-groups x 4 N-groups, warp tile 32x32).
// B stripes double-buffered via cp.async. __launch_bounds__(512) caps 128 regs
// (needs ~95; accum is 32 floats so no spill).
#define STG_STRIDE 272
__global__ __launch_bounds__(512) void k_wgemm_tc(const float* __restrict__ e2b) {
    extern __shared__ char dyn[];
    char* pA = dyn;                  // 32 KB
    char* pB0 = dyn + 32768;         // 32 KB
    char* pB1 = dyn + 65536;         // 32 KB
    char* pStage = dyn + 98304;      // 128 x 272 B

    int tid = threadIdx.x, wid = tid >> 5, lane = tid & 31;
    int m0 = blockIdx.x * 128;
    int wm = wid & 3;                // warp M: 0..3 (32 rows each)
    int wn = wid >> 2;               // warp N: 0..3 (32 cols each)

    uint32_t uA = smem_u32(pA);
    uint32_t uB[2] = {smem_u32(pB0), smem_u32(pB1)};

    copy_sw512_async(uB[0], g_e2);
    CP_COMMIT();
    copy_sw512(pA, g_h1 + (size_t)m0 * 128);

    int lrow = lane & 7;
    int lsel = lane >> 3;
    int a_row_off = (lsel & 1) * 8 + lrow;
    int a_chunk_sel = lsel >> 1;
    int b_row_off = (lsel >> 1) * 8 + lrow;
    int b_chunk_sel = lsel & 1;
    int g = lane >> 2, t4 = lane & 3;

    for (int s = 0; s < 32; s++) {
        CP_WAIT0();
        __syncthreads();             // B[s] visible; pStage drained
        if (s + 1 < 32) {
            copy_sw512_async(uB[(s + 1) & 1], g_e2 + (size_t)(s + 1) * 128 * 128);
            CP_COMMIT();
        }
        uint32_t uBc = uB[s & 1];

        float acc[2][4][4];
#pragma unroll
        for (int i = 0; i < 2; i++)
#pragma unroll
            for (int j = 0; j < 4; j++)
#pragma unroll
                for (int q = 0; q < 4; q++) acc[i][j][q] = 0.f;

#pragma unroll
        for (int ks = 0; ks < 8; ks++) {
            int c0 = ks * 2;
            uint32_t afr[2][4];
#pragma unroll
            for (int mt = 0; mt < 2; mt++) {
                int row = wm * 32 + mt * 16 + a_row_off;
                int ch = c0 + a_chunk_sel;
                uint32_t addr = uA + row * 256 + (((ch ^ (row & 7)) & 15) << 4);
                ldsm_x4(afr[mt][0], afr[mt][1], afr[mt][2], afr[mt][3], addr);
            }
            uint32_t bfr[2][4];
#pragma unroll
            for (int bt = 0; bt < 2; bt++) {
                int row = wn * 32 + bt * 16 + b_row_off;
                int ch = c0 + b_chunk_sel;
                uint32_t addr = uBc + row * 256 + (((ch ^ (row & 7)) & 15) << 4);
                ldsm_x4(bfr[bt][0], bfr[bt][1], bfr[bt][2], bfr[bt][3], addr);
            }
#pragma unroll
            for (int mt = 0; mt < 2; mt++)
#pragma unroll
                for (int nt = 0; nt < 4; nt++)
                    mma16816(acc[mt][nt], afr[mt], bfr[nt >> 1] + (nt & 1) * 2);
        }

        // staged epilogue: fp32 + bias -> bf16 -> smem -> coalesced GMEM
#pragma unroll
        for (int mt = 0; mt < 2; mt++) {
            int r0 = wm * 32 + mt * 16 + g;
#pragma unroll
            for (int nt = 0; nt < 4; nt++) {
                int col = wn * 32 + nt * 8 + t4 * 2;
                float b0 = e2b[s * 128 + col], b1 = e2b[s * 128 + col + 1];
                __nv_bfloat162 v0 = __floats2bfloat162_rn(acc[mt][nt][0] + b0, acc[mt][nt][1] + b1);
                __nv_bfloat162 v1 = __floats2bfloat162_rn(acc[mt][nt][2] + b0, acc[mt][nt][3] + b1);
                *(__nv_bfloat162*)(pStage + r0 * STG_STRIDE + col * 2) = v0;
                *(__nv_bfloat162*)(pStage + (r0 + 8) * STG_STRIDE + col * 2) = v1;
            }
        }
        __syncthreads();
#pragma unroll
        for (int it = 0; it < 4; it++) {
            int i = tid + it * 512;
            int row = i >> 4, ch = i & 15;
            uint4 v = *(const uint4*)(pStage + row * STG_STRIDE + ch * 16);
            *(uint4*)((char*)(g_Wb + (size_t)(m0 + row) * 4096 + s * 128) + ch * 16) = v;
        }
    }
}

// ---------------- prep: lin0 + zero state ---------------------------------
__global__ void k_prep(const float* __restrict__ x, const float* __restrict__ W,
                       const float* __restrict__ b) {
    int idx = blockIdx.x * blockDim.x + threadIdx.x;
    if (idx < NN * DD) {
        int n = idx >> 6, o = idx & 63;
        const float* xr = x + n * 14;
        const float* wr = W + o * 14;
        float acc = b[o];
#pragma unroll
        for (int i = 0; i < 14; i++) acc += xr[i] * wr[i];
        g_out[idx] = fmaxf(acc, 0.f);
        g_agg[idx] = 0.f;
    }
    if (idx < NN) g_cnt[idx] = 0.f;
    if (idx < NB) g_gcnt[idx] = 0;
}

// ---- edge MLP layer 1 (bf16 out) + e2_W cast -----------------------------
#define EP_T1 (NE * 128)
#define EP_T2 (4096 * 128)
__global__ void k_edgeprep(const float* __restrict__ ea, const float* __restrict__ W,
                           const float* __restrict__ b, const float* __restrict__ e2W) {
    int idx = blockIdx.x * blockDim.x + threadIdx.x;
    if (idx < EP_T1) {
        int e = idx >> 7, j = idx & 127;
        const float* er = ea + e * 4;
        const float* wr = W + j * 4;
        float acc = b[j];
#pragma unroll
        for (int i = 0; i < 4; i++) acc += er[i] * wr[i];
        g_h1[idx] = __float2bfloat16(fmaxf(acc, 0.f));
    } else {
        int k = idx - EP_T1;
        if (k < EP_T2) g_e2[k] = __float2bfloat16(e2W[k]);
    }
}

// ---- transpose small weight matrices (one-time) --------------------------
__global__ void k_wtrans(const float* __restrict__ gWih, const float* __restrict__ gWhh,
                         const float* __restrict__ lWih, const float* __restrict__ lWhh,
                         const float* __restrict__ fc1W) {
    int idx = blockIdx.x * blockDim.x + threadIdx.x;
    if (idx < 12288) {                       // gru Wih^T [64][192]
        int i = idx / 192, gate = idx % 192;
        g_gWihT[idx] = gWih[gate * 64 + i];
        g_gWhhT[idx] = gWhh[gate * 64 + i];
    } else if (idx < 12288 + 32768) {        // lstm Wih^T [128][256]
        int k = idx - 12288;
        int kk = k / 256, j = k % 256;
        g_lWihT[k] = lWih[j * 128 + kk];
    } else if (idx < 12288 + 32768 + 16384) {// lstm Whh^T [64][256]
        int k = idx - 12288 - 32768;
        int kk = k / 256, j = k % 256;
        g_lWhhT[k] = lWhh[j * 64 + kk];
    } else if (idx < 12288 + 32768 + 16384 + 16384) { // fc1^T [128][128]
        int k = idx - 12288 - 32768 - 16384;
        int kk = k / 128, j = k % 128;
        g_fc1T[k] = fc1W[j * 128 + kk];
    }
}

// ---------------- counting ------------------------------------------------
__global__ void k_cnt(const int* __restrict__ ei) {
    int e = blockIdx.x * blockDim.x + threadIdx.x;
    if (e < NE) atomicAdd(&g_cnt[ei[NE + e]], 1.f);
}
__global__ void k_gcnt(const int* __restrict__ batch) {
    int n = blockIdx.x * blockDim.x + threadIdx.x;
    if (n < NN) atomicAdd(&g_gcnt[batch[n]], 1);
}
__global__ void k_scan() {
    __shared__ int s[NB];
    int t = threadIdx.x;
    s[t] = g_gcnt[t];
    __syncthreads();
    for (int off = 1; off < NB; off <<= 1) {
        int v = (t >= off) ? s[t - off] : 0;
        __syncthreads();
        s[t] += v;
        __syncthreads();
    }
    g_gptr[t + 1] = s[t];
    if (t == 0) g_gptr[0] = 0;
}

// ---------------- messages: warp/edge, vectorized bf16 loads -------------
__global__ __launch_bounds__(256) void k_msg(const int* __restrict__ ei) {
    __shared__ float s[8][64];
    int tid = threadIdx.x, w = tid >> 5, l = tid & 31;
    int e0 = blockIdx.x * 8;
#pragma unroll
    for (int i = tid; i < 512; i += 256) {
        int el = i >> 6, c = i & 63;
        s[el][c] = g_out[ei[e0 + el] * 64 + c];
    }
    __syncthreads();
    int e = e0 + w;
    int dst = ei[NE + e];
    int co = (l & 7) * 8;
    int rb = l >> 3;
    float acc[8];
#pragma unroll
    for (int k = 0; k < 8; k++) acc[k] = 0.f;
    const __nv_bfloat16* Wr = g_Wb + (size_t)e * 4096;
#pragma unroll
    for (int r = 0; r < 16; r++) {
        int row = rb + r * 4;
        uint4 v = *(const uint4*)(Wr + row * 64 + co);
        float si = s[w][row];
        float2 f0 = __bfloat1622float2(*(__nv_bfloat162*)&v.x);
        float2 f1 = __bfloat1622float2(*(__nv_bfloat162*)&v.y);
        float2 f2 = __bfloat1622float2(*(__nv_bfloat162*)&v.z);
        float2 f3 = __bfloat1622float2(*(__nv_bfloat162*)&v.w);
        acc[0] += si * f0.x; acc[1] += si * f0.y;
        acc[2] += si * f1.x; acc[3] += si * f1.y;
        acc[4] += si * f2.x; acc[5] += si * f2.y;
        acc[6] += si * f3.x; acc[7] += si * f3.y;
    }
#pragma unroll
    for (int k = 0; k < 8; k++) {
        acc[k] += __shfl_xor_sync(0xffffffff, acc[k], 8);
        acc[k] += __shfl_xor_sync(0xffffffff, acc[k], 16);
    }
    int sub = l >> 3;
    atomicAdd(&g_agg[dst * 64 + co + sub * 2], acc[sub * 2]);
    atomicAdd(&g_agg[dst * 64 + co + sub * 2 + 1], acc[sub * 2 + 1]);
}

// ------- m = relu(agg/cnt + out@rootW + conv_b); zero agg for next iter ---
__global__ __launch_bounds__(256) void k_prem(const float* __restrict__ rootW,
                                              const float* __restrict__ convb) {
    __shared__ float sW[4096];
    int tid = threadIdx.x;
    for (int i = tid; i < 4096; i += 256) sW[i] = rootW[i];
    __syncthreads();
    int o = tid & 63, ln = tid >> 6;
    int base = blockIdx.x * 32;
    float cb = convb[o];
    for (int gg = 0; gg < 32; gg += 4) {
        int n = base + gg + ln;
        const float* orow = g_out + n * 64;
        float acc = 0.f;
#pragma unroll
        for (int i = 0; i < 64; i++) acc += orow[i] * sW[i * 64 + o];
        float c = g_cnt[n];
        if (c < 1.f) c = 1.f;
        float v = g_agg[n * 64 + o] / c + acc + cb;
        g_agg[n * 64 + o] = 0.f;
        g_m[n * 64 + o] = fmaxf(v, 0.f);
    }
}

// ---------------- GRU cell (transposed weights, 4 gates x 4 nodes/thread) -
__global__ __launch_bounds__(192) void k_gru(const float* __restrict__ bih,
                                             const float* __restrict__ bhh) {
    __shared__ float sm[16][66], sh[16][66], sgi[16][192], sgh[16][192];
    int tid = threadIdx.x;
    int base = blockIdx.x * 16;
    for (int i = tid; i < 1024; i += 192) {
        int n = i >> 6, c = i & 63;
        sm[n][c] = g_m[(base + n) * 64 + c];
        sh[n][c] = g_out[(base + n) * 64 + c];
    }
    __syncthreads();

    int gg = (tid % 48) * 4;
    int ng = (tid / 48) * 4;
    float accI[4][4], accH[4][4];
#pragma unroll
    for (int n = 0; n < 4; n++)
#pragma unroll
        for (int q = 0; q < 4; q++) { accI[n][q] = 0.f; accH[n][q] = 0.f; }

#pragma unroll 4
    for (int i = 0; i < 64; i++) {
        float4 wI = *(const float4*)(g_gWihT + i * 192 + gg);
        float4 wH = *(const float4*)(g_gWhhT + i * 192 + gg);
#pragma unroll
        for (int n = 0; n < 4; n++) {
            float mi = sm[ng + n][i], hi = sh[ng + n][i];
            accI[n][0] += mi * wI.x; accI[n][1] += mi * wI.y;
            accI[n][2] += mi * wI.z; accI[n][3] += mi * wI.w;
            accH[n][0] += hi * wH.x; accH[n][1] += hi * wH.y;
            accH[n][2] += hi * wH.z; accH[n][3] += hi * wH.w;
        }
    }
    float4 bi = *(const float4*)(bih + gg);
    float4 bh = *(const float4*)(bhh + gg);
#pragma unroll
    for (int n = 0; n < 4; n++) {
        sgi[ng + n][gg + 0] = accI[n][0] + bi.x;
        sgi[ng + n][gg + 1] = accI[n][1] + bi.y;
        sgi[ng + n][gg + 2] = accI[n][2] + bi.z;
        sgi[ng + n][gg + 3] = accI[n][3] + bi.w;
        sgh[ng + n][gg + 0] = accH[n][0] + bh.x;
        sgh[ng + n][gg + 1] = accH[n][1] + bh.y;
        sgh[ng + n][gg + 2] = accH[n][2] + bh.z;
        sgh[ng + n][gg + 3] = accH[n][3] + bh.w;
    }
    __syncthreads();
    for (int i = tid; i < 1024; i += 192) {
        int n = i >> 6, c = i & 63;
        float r = sigmoidf_(sgi[n][c] + sgh[n][c]);
        float z = sigmoidf_(sgi[n][64 + c] + sgh[n][64 + c]);
        float nn2 = tanhf(sgi[n][128 + c] + r * sgh[n][128 + c]);
        float hnew = (1.f - z) * nn2 + z * sh[n][c];
        g_out[(base + n) * 64 + c] = hnew;
    }
}

// ====== fused Set2Set (3 steps) + final head; block = 1 graph =============
__global__ __launch_bounds__(256) void k_s2s(const float* __restrict__ lbih,
                                             const float* __restrict__ lbhh,
                                             const float* __restrict__ fc1b,
                                             const float* __restrict__ fc2W,
                                             const float* __restrict__ fc2b,
                                             float* __restrict__ outp) {
    __shared__ float qstar[128], shl[64], scl[64], sg[256], sa[256];
    int g = blockIdx.x, j = threadIdx.x;
    int s = g_gptr[g], e2 = g_gptr[g + 1];
    int cnt = e2 - s;
    if (j < 128) qstar[j] = 0.f;
    if (j < 64) { shl[j] = 0.f; scl[j] = 0.f; }
    __syncthreads();

    for (int step = 0; step < 3; step++) {
        // LSTM gates (transposed weights, coalesced)
        float acc = lbih[j] + lbhh[j];
#pragma unroll 8
        for (int k = 0; k < 128; k++) acc += qstar[k] * g_lWihT[k * 256 + j];
#pragma unroll 8
        for (int k = 0; k < 64; k++) acc += shl[k] * g_lWhhT[k * 256 + j];
        sg[j] = acc;
        __syncthreads();
        if (j < 64) {
            float i_ = sg[j], f_ = sg[64 + j], gg_ = sg[128 + j], o_ = sg[192 + j];
            float c = sigmoidf_(f_) * scl[j] + sigmoidf_(i_) * tanhf(gg_);
            float h = sigmoidf_(o_) * tanhf(c);
            scl[j] = c;
            shl[j] = h;
        }
        __syncthreads();
        // attention logits (node-parallel) + per-thread max
        float mymax = -3.0e38f;
        for (int n = j; n < cnt; n += 256) {
            const float* orow = g_out + (size_t)(s + n) * 64;
            float d = 0.f;
#pragma unroll
            for (int i = 0; i < 64; i++) d += orow[i] * shl[i];
            sa[n] = d;
            mymax = fmaxf(mymax, d);
        }
        sg[j] = mymax;
        __syncthreads();
        for (int st = 128; st > 0; st >>= 1) {
            if (j < st) sg[j] = fmaxf(sg[j], sg[j + st]);
            __syncthreads();
        }
        float mx = sg[0];
        __syncthreads();
        float mysum = 0.f;
        for (int n = j; n < cnt; n += 256) {
            float ex = expf(sa[n] - mx);
            sa[n] = ex;
            mysum += ex;
        }
        sg[j] = mysum;
        __syncthreads();
        for (int st = 128; st > 0; st >>= 1) {
            if (j < st) sg[j] += sg[j + st];
            __syncthreads();
        }
        float den = sg[0];
        __syncthreads();
        // readout (feature-parallel)
        if (j < 64) {
            float r = 0.f;
            for (int n = 0; n < cnt; n++) r += sa[n] * g_out[(size_t)(s + n) * 64 + j];
            if (cnt > 0) r /= den;
            qstar[j] = shl[j];
            qstar[64 + j] = r;
        }
        __syncthreads();
    }

    // final head: fc2(relu(fc1(qstar)))
    float val = 0.f;
    if (j < 128) {
        float a = fc1b[j];
#pragma unroll 8
        for (int k = 0; k < 128; k++) a += qstar[k] * g_fc1T[k * 128 + j];
        val = fmaxf(a, 0.f) * fc2W[j];
    }
    sg[j] = val;
    __syncthreads();
    for (int st = 128; st > 0; st >>= 1) {
        if (j < st) sg[j] += sg[j + st];
        __syncthreads();
    }
    if (j == 0) outp[g] = sg[0] + fc2b[0];
}

// ---------------- host: launch sequence ----------------------------------
extern "C" void kernel_launch(void* const* d_in, const int* in_sizes, int n_in,
                              void* d_out, int out_size) {
    const float* x       = (const float*)d_in[0];
    const int*   ei      = (const int*)d_in[1];
    const float* ea      = (const float*)d_in[2];
    const int*   batch   = (const int*)d_in[3];
    const float* lin0_W  = (const float*)d_in[4];
    const float* lin0_b  = (const float*)d_in[5];
    const float* e1_W    = (const float*)d_in[6];
    const float* e1_b    = (const float*)d_in[7];
    const float* e2_W    = (const float*)d_in[8];
    const float* e2_b    = (const float*)d_in[9];
    const float* root_W  = (const float*)d_in[10];
    const float* conv_b  = (const float*)d_in[11];
    const float* gru_Wih = (const float*)d_in[12];
    const float* gru_Whh = (const float*)d_in[13];
    const float* gru_bih = (const float*)d_in[14];
    const float* gru_bhh = (const float*)d_in[15];
    const float* lstm_Wih = (const float*)d_in[16];
    const float* lstm_Whh = (const float*)d_in[17];
    const float* lstm_bih = (const float*)d_in[18];
    const float* lstm_bhh = (const float*)d_in[19];
    const float* fc1_W   = (const float*)d_in[20];
    const float* fc1_b   = (const float*)d_in[21];
    const float* fc2_W   = (const float*)d_in[22];
    const float* fc2_b   = (const float*)d_in[23];
    float* outp = (float*)d_out;

    static bool attr_set = false;
    const int WG_SMEM = 98304 + 128 * STG_STRIDE;    // 133,120 B
    if (!attr_set) {
        cudaFuncSetAttribute(k_wgemm_tc, cudaFuncAttributeMaxDynamicSharedMemorySize, WG_SMEM);
        attr_set = true;
    }

    // k_wgemm_tc in slot #4 — the launch position ncu's window captures.
    k_prep<<<(NN * DD) / 256, 256>>>(x, lin0_W, lin0_b);
    k_edgeprep<<<(EP_T1 + EP_T2) / 256, 256>>>(ea, e1_W, e1_b, e2_W);
    k_wtrans<<<(12288 + 32768 + 16384 + 16384 + 255) / 256, 256>>>(
        gru_Wih, gru_Whh, lstm_Wih, lstm_Whh, fc1_W);
    k_wgemm_tc<<<NE / 128, 512, WG_SMEM>>>(e2_b);
    k_cnt<<<NE / 256, 256>>>(ei);
    k_gcnt<<<NN / 256, 256>>>(batch);
    k_scan<<<1, NB>>>();

    for (int it = 0; it < 3; it++) {
        k_msg<<<NE / 8, 256>>>(ei);
        k_prem<<<NN / 32, 256>>>(root_W, conv_b);
        k_gru<<<NN / 16, 192>>>(gru_bih, gru_bhh);
    }

    k_s2s<<<NB, 256>>>(lstm_bih, lstm_bhh, fc1_b, fc2_W, fc2_b, outp);
}

// round 10
// speedup vs baseline: 3.6520x; 1.1274x over previous
#include <cuda_runtime.h>
#include <cuda_bf16.h>
#include <math.h>
#include <cstdint>

#define NN 32768
#define NE 49152
#define NB 1024
#define DD 64

// ---------------- device scratch (no allocations allowed) ----------------
__device__ __nv_bfloat16 g_h1[(size_t)NE * 128];    // edge MLP hidden (bf16)
__device__ __nv_bfloat16 g_e2[4096 * 128];          // e2_W (bf16)
__device__ __nv_bfloat16 g_Wb[(size_t)NE * 4096];   // edge weights (bf16, 402 MB)
__device__ float g_out[NN * DD];                    // node features / GRU h
__device__ float g_agg[NN * DD];                    // message accumulator
__device__ float g_cnt[NN];                         // in-degree (float)
__device__ int   g_gcnt[NB];                        // nodes per graph
__device__ int   g_gptr[NB + 1];                    // CSR over sorted batch
// transposed small weights (coalesced lane-consecutive access)
__device__ float g_gWihT[64 * 192];                 // gru Wih^T  [i][gate]
__device__ float g_gWhhT[64 * 192];                 // gru Whh^T
__device__ float g_lWihT[128 * 256];                // lstm Wih^T [k][gate]
__device__ float g_lWhhT[64 * 256];                 // lstm Whh^T
__device__ float g_fc1T[128 * 128];                 // fc1^T      [k][gate]

__device__ __forceinline__ float sigmoidf_(float x) { return 1.f / (1.f + expf(-x)); }

__device__ __forceinline__ uint32_t smem_u32(const void* p) {
    uint32_t a;
    asm("{ .reg .u64 t; cvta.to.shared.u64 t, %1; cvt.u32.u64 %0, t; }" : "=r"(a) : "l"(p));
    return a;
}
__device__ __forceinline__ void ldsm_x4(uint32_t& r0, uint32_t& r1, uint32_t& r2, uint32_t& r3,
                                        uint32_t addr) {
    asm volatile("ldmatrix.sync.aligned.m8n8.x4.shared.b16 {%0, %1, %2, %3}, [%4];"
                 : "=r"(r0), "=r"(r1), "=r"(r2), "=r"(r3) : "r"(addr));
}
__device__ __forceinline__ void mma16816(float* d, const uint32_t* a, const uint32_t* b) {
    asm volatile(
        "mma.sync.aligned.m16n8k16.row.col.f32.bf16.bf16.f32 "
        "{%0, %1, %2, %3}, {%4, %5, %6, %7}, {%8, %9}, {%0, %1, %2, %3};"
        : "+f"(d[0]), "+f"(d[1]), "+f"(d[2]), "+f"(d[3])
        : "r"(a[0]), "r"(a[1]), "r"(a[2]), "r"(a[3]), "r"(b[0]), "r"(b[1]));
}

// copy a [128 x 128 bf16] tile into smem with 16B-chunk XOR swizzle (512 thr)
__device__ __forceinline__ void copy_sw512(char* dst, const __nv_bfloat16* __restrict__ src) {
    int tid = threadIdx.x;
#pragma unroll
    for (int it = 0; it < 4; it++) {
        int i = tid + it * 512;
        int row = i >> 4;
        int chunk = i & 15;
        uint4 v = *(const uint4*)(src + (size_t)row * 128 + chunk * 8);
        *(uint4*)(dst + row * 256 + ((chunk ^ (row & 7)) << 4)) = v;
    }
}
__device__ __forceinline__ void copy_sw512_async(uint32_t dst, const __nv_bfloat16* __restrict__ src) {
    int tid = threadIdx.x;
#pragma unroll
    for (int it = 0; it < 4; it++) {
        int i = tid + it * 512;
        int row = i >> 4;
        int chunk = i & 15;
        uint32_t d = dst + row * 256 + ((chunk ^ (row & 7)) << 4);
        asm volatile("cp.async.cg.shared.global [%0], [%1], 16;"
                     :: "r"(d), "l"(src + (size_t)row * 128 + chunk * 8));
    }
}
#define CP_COMMIT() asm volatile("cp.async.commit_group;" ::: "memory")
#define CP_WAIT0()  asm volatile("cp.async.wait_group 0;" ::: "memory")

// ============ W GEMM (HMMA, 1-pass bf16): g_Wb = bf16(h1 @ e2^T + b) ======
#define STG_STRIDE 272
__global__ __launch_bounds__(512) void k_wgemm_tc(const float* __restrict__ e2b) {
    extern __shared__ char dyn[];
    char* pA = dyn;
    char* pB0 = dyn + 32768;
    char* pB1 = dyn + 65536;
    char* pStage = dyn + 98304;

    int tid = threadIdx.x, wid = tid >> 5, lane = tid & 31;
    int m0 = blockIdx.x * 128;
    int wm = wid & 3;
    int wn = wid >> 2;

    uint32_t uA = smem_u32(pA);
    uint32_t uB[2] = {smem_u32(pB0), smem_u32(pB1)};

    copy_sw512_async(uB[0], g_e2);
    CP_COMMIT();
    copy_sw512(pA, g_h1 + (size_t)m0 * 128);

    int lrow = lane & 7;
    int lsel = lane >> 3;
    int a_row_off = (lsel & 1) * 8 + lrow;
    int a_chunk_sel = lsel >> 1;
    int b_row_off = (lsel >> 1) * 8 + lrow;
    int b_chunk_sel = lsel & 1;
    int g = lane >> 2, t4 = lane & 3;

    for (int s = 0; s < 32; s++) {
        CP_WAIT0();
        __syncthreads();
        if (s + 1 < 32) {
            copy_sw512_async(uB[(s + 1) & 1], g_e2 + (size_t)(s + 1) * 128 * 128);
            CP_COMMIT();
        }
        uint32_t uBc = uB[s & 1];

        float acc[2][4][4];
#pragma unroll
        for (int i = 0; i < 2; i++)
#pragma unroll
            for (int j = 0; j < 4; j++)
#pragma unroll
                for (int q = 0; q < 4; q++) acc[i][j][q] = 0.f;

#pragma unroll
        for (int ks = 0; ks < 8; ks++) {
            int c0 = ks * 2;
            uint32_t afr[2][4];
#pragma unroll
            for (int mt = 0; mt < 2; mt++) {
                int row = wm * 32 + mt * 16 + a_row_off;
                int ch = c0 + a_chunk_sel;
                uint32_t addr = uA + row * 256 + (((ch ^ (row & 7)) & 15) << 4);
                ldsm_x4(afr[mt][0], afr[mt][1], afr[mt][2], afr[mt][3], addr);
            }
            uint32_t bfr[2][4];
#pragma unroll
            for (int bt = 0; bt < 2; bt++) {
                int row = wn * 32 + bt * 16 + b_row_off;
                int ch = c0 + b_chunk_sel;
                uint32_t addr = uBc + row * 256 + (((ch ^ (row & 7)) & 15) << 4);
                ldsm_x4(bfr[bt][0], bfr[bt][1], bfr[bt][2], bfr[bt][3], addr);
            }
#pragma unroll
            for (int mt = 0; mt < 2; mt++)
#pragma unroll
                for (int nt = 0; nt < 4; nt++)
                    mma16816(acc[mt][nt], afr[mt], bfr[nt >> 1] + (nt & 1) * 2);
        }

#pragma unroll
        for (int mt = 0; mt < 2; mt++) {
            int r0 = wm * 32 + mt * 16 + g;
#pragma unroll
            for (int nt = 0; nt < 4; nt++) {
                int col = wn * 32 + nt * 8 + t4 * 2;
                float b0 = e2b[s * 128 + col], b1 = e2b[s * 128 + col + 1];
                __nv_bfloat162 v0 = __floats2bfloat162_rn(acc[mt][nt][0] + b0, acc[mt][nt][1] + b1);
                __nv_bfloat162 v1 = __floats2bfloat162_rn(acc[mt][nt][2] + b0, acc[mt][nt][3] + b1);
                *(__nv_bfloat162*)(pStage + r0 * STG_STRIDE + col * 2) = v0;
                *(__nv_bfloat162*)(pStage + (r0 + 8) * STG_STRIDE + col * 2) = v1;
            }
        }
        __syncthreads();
#pragma unroll
        for (int it = 0; it < 4; it++) {
            int i = tid + it * 512;
            int row = i >> 4, ch = i & 15;
            uint4 v = *(const uint4*)(pStage + row * STG_STRIDE + ch * 16);
            *(uint4*)((char*)(g_Wb + (size_t)(m0 + row) * 4096 + s * 128) + ch * 16) = v;
        }
    }
}

// ---------------- prep: lin0 + zero state ---------------------------------
__global__ void k_prep(const float* __restrict__ x, const float* __restrict__ W,
                       const float* __restrict__ b) {
    int idx = blockIdx.x * blockDim.x + threadIdx.x;
    if (idx < NN * DD) {
        int n = idx >> 6, o = idx & 63;
        const float* xr = x + n * 14;
        const float* wr = W + o * 14;
        float acc = b[o];
#pragma unroll
        for (int i = 0; i < 14; i++) acc += xr[i] * wr[i];
        g_out[idx] = fmaxf(acc, 0.f);
        g_agg[idx] = 0.f;
    }
    if (idx < NN) g_cnt[idx] = 0.f;
    if (idx < NB) g_gcnt[idx] = 0;
}

// ---- edge MLP layer 1 (bf16) + e2_W cast + small-weight transposes -------
#define EP_T1 (NE * 128)
#define EP_T2 (4096 * 128)
#define EP_T3 (12288 + 32768 + 16384 + 16384)
__global__ void k_edgeprep(const float* __restrict__ ea, const float* __restrict__ W,
                           const float* __restrict__ b, const float* __restrict__ e2W,
                           const float* __restrict__ gWih, const float* __restrict__ gWhh,
                           const float* __restrict__ lWih, const float* __restrict__ lWhh,
                           const float* __restrict__ fc1W) {
    int idx = blockIdx.x * blockDim.x + threadIdx.x;
    if (idx < EP_T1) {
        int e = idx >> 7, j = idx & 127;
        const float* er = ea + e * 4;
        const float* wr = W + j * 4;
        float acc = b[j];
#pragma unroll
        for (int i = 0; i < 4; i++) acc += er[i] * wr[i];
        g_h1[idx] = __float2bfloat16(fmaxf(acc, 0.f));
    } else if (idx < EP_T1 + EP_T2) {
        int k = idx - EP_T1;
        g_e2[k] = __float2bfloat16(e2W[k]);
    } else {
        int t = idx - EP_T1 - EP_T2;
        if (t < 12288) {
            int i = t / 192, gate = t % 192;
            g_gWihT[t] = gWih[gate * 64 + i];
            g_gWhhT[t] = gWhh[gate * 64 + i];
        } else if (t < 12288 + 32768) {
            int k = t - 12288;
            g_lWihT[k] = lWih[(k % 256) * 128 + k / 256];
        } else if (t < 12288 + 32768 + 16384) {
            int k = t - 12288 - 32768;
            g_lWhhT[k] = lWhh[(k % 256) * 64 + k / 256];
        } else if (t < EP_T3) {
            int k = t - 12288 - 32768 - 16384;
            g_fc1T[k] = fc1W[(k % 128) * 128 + k / 128];
        }
    }
}

// ---------------- counts (in-degree + graph sizes) ------------------------
__global__ void k_counts(const int* __restrict__ ei, const int* __restrict__ batch) {
    int i = blockIdx.x * blockDim.x + threadIdx.x;
    if (i < NE) atomicAdd(&g_cnt[ei[NE + i]], 1.f);
    if (i < NN) atomicAdd(&g_gcnt[batch[i]], 1);
}
__global__ void k_scan() {
    __shared__ int s[NB];
    int t = threadIdx.x;
    s[t] = g_gcnt[t];
    __syncthreads();
    for (int off = 1; off < NB; off <<= 1) {
        int v = (t >= off) ? s[t - off] : 0;
        __syncthreads();
        s[t] += v;
        __syncthreads();
    }
    g_gptr[t + 1] = s[t];
    if (t == 0) g_gptr[0] = 0;
}

// ---------------- messages: warp/edge, vectorized bf16 loads -------------
__global__ __launch_bounds__(256) void k_msg(const int* __restrict__ ei) {
    __shared__ float s[8][64];
    int tid = threadIdx.x, w = tid >> 5, l = tid & 31;
    int e0 = blockIdx.x * 8;
#pragma unroll
    for (int i = tid; i < 512; i += 256) {
        int el = i >> 6, c = i & 63;
        s[el][c] = g_out[ei[e0 + el] * 64 + c];
    }
    __syncthreads();
    int e = e0 + w;
    int dst = ei[NE + e];
    int co = (l & 7) * 8;
    int rb = l >> 3;
    float acc[8];
#pragma unroll
    for (int k = 0; k < 8; k++) acc[k] = 0.f;
    const __nv_bfloat16* Wr = g_Wb + (size_t)e * 4096;
#pragma unroll
    for (int r = 0; r < 16; r++) {
        int row = rb + r * 4;
        uint4 v = *(const uint4*)(Wr + row * 64 + co);
        float si = s[w][row];
        float2 f0 = __bfloat1622float2(*(__nv_bfloat162*)&v.x);
        float2 f1 = __bfloat1622float2(*(__nv_bfloat162*)&v.y);
        float2 f2 = __bfloat1622float2(*(__nv_bfloat162*)&v.z);
        float2 f3 = __bfloat1622float2(*(__nv_bfloat162*)&v.w);
        acc[0] += si * f0.x; acc[1] += si * f0.y;
        acc[2] += si * f1.x; acc[3] += si * f1.y;
        acc[4] += si * f2.x; acc[5] += si * f2.y;
        acc[6] += si * f3.x; acc[7] += si * f3.y;
    }
#pragma unroll
    for (int k = 0; k < 8; k++) {
        acc[k] += __shfl_xor_sync(0xffffffff, acc[k], 8);
        acc[k] += __shfl_xor_sync(0xffffffff, acc[k], 16);
    }
    int sub = l >> 3;
    atomicAdd(&g_agg[dst * 64 + co + sub * 2], acc[sub * 2]);
    atomicAdd(&g_agg[dst * 64 + co + sub * 2 + 1], acc[sub * 2 + 1]);
}

// ====== fused node update: m = relu(agg/cnt + h@rootW + cb); GRU ==========
// 64 nodes per block, 256 threads. h and m staged in smem; GRU runs in four
// 16-node sub-batches (transposed weights; L1-cached after first pass).
#define ND_SMEM ((4096 + 2 * 64 * 66 + 2 * 16 * 192) * 4)
__global__ __launch_bounds__(256) void k_nodeup(const float* __restrict__ rootW,
                                                const float* __restrict__ convb,
                                                const float* __restrict__ bih,
                                                const float* __restrict__ bhh) {
    extern __shared__ float sdyn[];
    float* sW = sdyn;                       // 4096
    float* sm_ = sdyn + 4096;               // 64 x 66
    float* sh_ = sm_ + 64 * 66;             // 64 x 66
    float* sgi = sh_ + 64 * 66;             // 16 x 192
    float* sgh = sgi + 16 * 192;            // 16 x 192
    int tid = threadIdx.x;
    int base = blockIdx.x * 64;

    for (int i = tid; i < 4096; i += 256) {
        sW[i] = rootW[i];
        int n = i >> 6, c = i & 63;
        sh_[n * 66 + c] = g_out[(base + n) * 64 + c];
    }
    __syncthreads();

    // ---- conv combine: m
    {
        int o = tid & 63, ln = tid >> 6;
        float cb = convb[o];
        for (int g4 = 0; g4 < 16; g4++) {
            int n = g4 * 4 + ln;
            const float* hr = sh_ + n * 66;
            float acc = 0.f;
#pragma unroll
            for (int i = 0; i < 64; i++) acc += hr[i] * sW[i * 64 + o];
            int node = base + n;
            float c = g_cnt[node];
            if (c < 1.f) c = 1.f;
            float v = g_agg[node * 64 + o] / c + acc + cb;
            g_agg[node * 64 + o] = 0.f;
            sm_[n * 66 + o] = fmaxf(v, 0.f);
        }
    }
    __syncthreads();

    // ---- GRU in 4 sub-batches of 16 nodes
    int gg = (tid % 48) * 4;
    int ng = (tid / 48) * 4;
    for (int nb = 0; nb < 4; nb++) {
        int nbase = nb * 16;
        if (tid < 192) {
            float accI[4][4], accH[4][4];
#pragma unroll
            for (int n = 0; n < 4; n++)
#pragma unroll
                for (int q = 0; q < 4; q++) { accI[n][q] = 0.f; accH[n][q] = 0.f; }
#pragma unroll 4
            for (int i = 0; i < 64; i++) {
                float4 wI = *(const float4*)(g_gWihT + i * 192 + gg);
                float4 wH = *(const float4*)(g_gWhhT + i * 192 + gg);
#pragma unroll
                for (int n = 0; n < 4; n++) {
                    float mi = sm_[(nbase + ng + n) * 66 + i];
                    float hi = sh_[(nbase + ng + n) * 66 + i];
                    accI[n][0] += mi * wI.x; accI[n][1] += mi * wI.y;
                    accI[n][2] += mi * wI.z; accI[n][3] += mi * wI.w;
                    accH[n][0] += hi * wH.x; accH[n][1] += hi * wH.y;
                    accH[n][2] += hi * wH.z; accH[n][3] += hi * wH.w;
                }
            }
            float4 bi = *(const float4*)(bih + gg);
            float4 bh = *(const float4*)(bhh + gg);
#pragma unroll
            for (int n = 0; n < 4; n++) {
                float* pi = sgi + (ng + n) * 192 + gg;
                float* ph = sgh + (ng + n) * 192 + gg;
                pi[0] = accI[n][0] + bi.x; pi[1] = accI[n][1] + bi.y;
                pi[2] = accI[n][2] + bi.z; pi[3] = accI[n][3] + bi.w;
                ph[0] = accH[n][0] + bh.x; ph[1] = accH[n][1] + bh.y;
                ph[2] = accH[n][2] + bh.z; ph[3] = accH[n][3] + bh.w;
            }
        }
        __syncthreads();
        for (int i = tid; i < 1024; i += 256) {
            int n = i >> 6, c = i & 63;
            float r = sigmoidf_(sgi[n * 192 + c] + sgh[n * 192 + c]);
            float z = sigmoidf_(sgi[n * 192 + 64 + c] + sgh[n * 192 + 64 + c]);
            float nn2 = tanhf(sgi[n * 192 + 128 + c] + r * sgh[n * 192 + 128 + c]);
            float hnew = (1.f - z) * nn2 + z * sh_[(nbase + n) * 66 + c];
            g_out[(base + nbase + n) * 64 + c] = hnew;
        }
        __syncthreads();
    }
}

// ====== fused Set2Set (3 steps) + final head; block = 1 graph =============
__global__ __launch_bounds__(256) void k_s2s(const float* __restrict__ lbih,
                                             const float* __restrict__ lbhh,
                                             const float* __restrict__ fc1b,
                                             const float* __restrict__ fc2W,
                                             const float* __restrict__ fc2b,
                                             float* __restrict__ outp) {
    __shared__ float qstar[128], shl[64], scl[64], sg[256], sa[256];
    int g = blockIdx.x, j = threadIdx.x;
    int s = g_gptr[g], e2 = g_gptr[g + 1];
    int cnt = e2 - s;
    if (j < 128) qstar[j] = 0.f;
    if (j < 64) { shl[j] = 0.f; scl[j] = 0.f; }
    __syncthreads();

    for (int step = 0; step < 3; step++) {
        float acc = lbih[j] + lbhh[j];
#pragma unroll 8
        for (int k = 0; k < 128; k++) acc += qstar[k] * g_lWihT[k * 256 + j];
#pragma unroll 8
        for (int k = 0; k < 64; k++) acc += shl[k] * g_lWhhT[k * 256 + j];
        sg[j] = acc;
        __syncthreads();
        if (j < 64) {
            float i_ = sg[j], f_ = sg[64 + j], gg_ = sg[128 + j], o_ = sg[192 + j];
            float c = sigmoidf_(f_) * scl[j] + sigmoidf_(i_) * tanhf(gg_);
            float h = sigmoidf_(o_) * tanhf(c);
            scl[j] = c;
            shl[j] = h;
        }
        __syncthreads();
        float mymax = -3.0e38f;
        for (int n = j; n < cnt; n += 256) {
            const float* orow = g_out + (size_t)(s + n) * 64;
            float d = 0.f;
#pragma unroll
            for (int i = 0; i < 64; i++) d += orow[i] * shl[i];
            sa[n] = d;
            mymax = fmaxf(mymax, d);
        }
        sg[j] = mymax;
        __syncthreads();
        for (int st = 128; st > 0; st >>= 1) {
            if (j < st) sg[j] = fmaxf(sg[j], sg[j + st]);
            __syncthreads();
        }
        float mx = sg[0];
        __syncthreads();
        float mysum = 0.f;
        for (int n = j; n < cnt; n += 256) {
            float ex = expf(sa[n] - mx);
            sa[n] = ex;
            mysum += ex;
        }
        sg[j] = mysum;
        __syncthreads();
        for (int st = 128; st > 0; st >>= 1) {
            if (j < st) sg[j] += sg[j + st];
            __syncthreads();
        }
        float den = sg[0];
        __syncthreads();
        if (j < 64) {
            float r = 0.f;
            for (int n = 0; n < cnt; n++) r += sa[n] * g_out[(size_t)(s + n) * 64 + j];
            if (cnt > 0) r /= den;
            qstar[j] = shl[j];
            qstar[64 + j] = r;
        }
        __syncthreads();
    }

    float val = 0.f;
    if (j < 128) {
        float a = fc1b[j];
#pragma unroll 8
        for (int k = 0; k < 128; k++) a += qstar[k] * g_fc1T[k * 128 + j];
        val = fmaxf(a, 0.f) * fc2W[j];
    }
    sg[j] = val;
    __syncthreads();
    for (int st = 128; st > 0; st >>= 1) {
        if (j < st) sg[j] += sg[j + st];
        __syncthreads();
    }
    if (j == 0) outp[g] = sg[0] + fc2b[0];
}

// ---------------- host: launch sequence ----------------------------------
extern "C" void kernel_launch(void* const* d_in, const int* in_sizes, int n_in,
                              void* d_out, int out_size) {
    const float* x       = (const float*)d_in[0];
    const int*   ei      = (const int*)d_in[1];
    const float* ea      = (const float*)d_in[2];
    const int*   batch   = (const int*)d_in[3];
    const float* lin0_W  = (const float*)d_in[4];
    const float* lin0_b  = (const float*)d_in[5];
    const float* e1_W    = (const float*)d_in[6];
    const float* e1_b    = (const float*)d_in[7];
    const float* e2_W    = (const float*)d_in[8];
    const float* e2_b    = (const float*)d_in[9];
    const float* root_W  = (const float*)d_in[10];
    const float* conv_b  = (const float*)d_in[11];
    const float* gru_Wih = (const float*)d_in[12];
    const float* gru_Whh = (const float*)d_in[13];
    const float* gru_bih = (const float*)d_in[14];
    const float* gru_bhh = (const float*)d_in[15];
    const float* lstm_Wih = (const float*)d_in[16];
    const float* lstm_Whh = (const float*)d_in[17];
    const float* lstm_bih = (const float*)d_in[18];
    const float* lstm_bhh = (const float*)d_in[19];
    const float* fc1_W   = (const float*)d_in[20];
    const float* fc1_b   = (const float*)d_in[21];
    const float* fc2_W   = (const float*)d_in[22];
    const float* fc2_b   = (const float*)d_in[23];
    float* outp = (float*)d_out;

    static bool attr_set = false;
    const int WG_SMEM = 98304 + 128 * STG_STRIDE;    // 133,120 B
    if (!attr_set) {
        cudaFuncSetAttribute(k_wgemm_tc, cudaFuncAttributeMaxDynamicSharedMemorySize, WG_SMEM);
        cudaFuncSetAttribute(k_nodeup, cudaFuncAttributeMaxDynamicSharedMemorySize, ND_SMEM);
        attr_set = true;
    }

    // k_wgemm_tc in slot #4 — the launch position ncu's window captures.
    k_prep<<<(NN * DD) / 256, 256>>>(x, lin0_W, lin0_b);
    k_edgeprep<<<(EP_T1 + EP_T2 + EP_T3 + 255) / 256, 256>>>(
        ea, e1_W, e1_b, e2_W, gru_Wih, gru_Whh, lstm_Wih, lstm_Whh, fc1_W);
    k_counts<<<NE / 256, 256>>>(ei, batch);
    k_wgemm_tc<<<NE / 128, 512, WG_SMEM>>>(e2_b);
    k_scan<<<1, NB>>>();

    for (int it = 0; it < 3; it++) {
        k_msg<<<NE / 8, 256>>>(ei);
        k_nodeup<<<NN / 64, 256, ND_SMEM>>>(root_W, conv_b, gru_bih, gru_bhh);
    }

    k_s2s<<<NB, 256>>>(lstm_bih, lstm_bhh, fc1_b, fc2_W, fc2_b, outp);
}

// round 11
// speedup vs baseline: 3.6558x; 1.0010x over previous
#include <cuda_runtime.h>
#include <cuda_bf16.h>
#include <math.h>
#include <cstdint>

#define NN 32768
#define NE 49152
#define NB 1024
#define DD 64

// ---------------- device scratch (no allocations allowed) ----------------
__device__ __nv_bfloat16 g_h1[(size_t)NE * 128];    // edge MLP hidden (bf16)
__device__ __nv_bfloat16 g_e2[4096 * 128];          // e2_W (bf16)
__device__ __nv_bfloat16 g_Wb[(size_t)NE * 4096];   // edge weights (bf16, 402 MB)
__device__ float g_out[NN * DD];                    // node features / GRU h
__device__ float g_agg[NN * DD];                    // message accumulator
__device__ float g_cnt[NN];                         // in-degree (float)
__device__ int   g_gcnt[NB];                        // nodes per graph
__device__ int   g_gptr[NB + 1];                    // CSR over sorted batch
// transposed small weights
__device__ float g_gWihT[64 * 192];                 // gru Wih^T  [i][gate] (fp32)
__device__ float g_gWhhT[64 * 192];                 // gru Whh^T
__device__ __nv_bfloat16 g_lWihTb[128 * 256];       // lstm Wih^T (bf16, L1-resident)
__device__ __nv_bfloat16 g_lWhhTb[64 * 256];        // lstm Whh^T (bf16)
__device__ __nv_bfloat16 g_fc1Tb[128 * 128];        // fc1^T      (bf16)

__device__ __forceinline__ float sigmoidf_(float x) { return 1.f / (1.f + expf(-x)); }

__device__ __forceinline__ uint32_t smem_u32(const void* p) {
    uint32_t a;
    asm("{ .reg .u64 t; cvta.to.shared.u64 t, %1; cvt.u32.u64 %0, t; }" : "=r"(a) : "l"(p));
    return a;
}
__device__ __forceinline__ void ldsm_x4(uint32_t& r0, uint32_t& r1, uint32_t& r2, uint32_t& r3,
                                        uint32_t addr) {
    asm volatile("ldmatrix.sync.aligned.m8n8.x4.shared.b16 {%0, %1, %2, %3}, [%4];"
                 : "=r"(r0), "=r"(r1), "=r"(r2), "=r"(r3) : "r"(addr));
}
__device__ __forceinline__ void mma16816(float* d, const uint32_t* a, const uint32_t* b) {
    asm volatile(
        "mma.sync.aligned.m16n8k16.row.col.f32.bf16.bf16.f32 "
        "{%0, %1, %2, %3}, {%4, %5, %6, %7}, {%8, %9}, {%0, %1, %2, %3};"
        : "+f"(d[0]), "+f"(d[1]), "+f"(d[2]), "+f"(d[3])
        : "r"(a[0]), "r"(a[1]), "r"(a[2]), "r"(a[3]), "r"(b[0]), "r"(b[1]));
}

// copy a [128 x 128 bf16] tile into smem with 16B-chunk XOR swizzle (512 thr)
__device__ __forceinline__ void copy_sw512(char* dst, const __nv_bfloat16* __restrict__ src) {
    int tid = threadIdx.x;
#pragma unroll
    for (int it = 0; it < 4; it++) {
        int i = tid + it * 512;
        int row = i >> 4;
        int chunk = i & 15;
        uint4 v = *(const uint4*)(src + (size_t)row * 128 + chunk * 8);
        *(uint4*)(dst + row * 256 + ((chunk ^ (row & 7)) << 4)) = v;
    }
}
__device__ __forceinline__ void copy_sw512_async(uint32_t dst, const __nv_bfloat16* __restrict__ src) {
    int tid = threadIdx.x;
#pragma unroll
    for (int it = 0; it < 4; it++) {
        int i = tid + it * 512;
        int row = i >> 4;
        int chunk = i & 15;
        uint32_t d = dst + row * 256 + ((chunk ^ (row & 7)) << 4);
        asm volatile("cp.async.cg.shared.global [%0], [%1], 16;"
                     :: "r"(d), "l"(src + (size_t)row * 128 + chunk * 8));
    }
}
#define CP_COMMIT() asm volatile("cp.async.commit_group;" ::: "memory")
#define CP_WAIT0()  asm volatile("cp.async.wait_group 0;" ::: "memory")

// ============ W GEMM (HMMA, 1-pass bf16): g_Wb = bf16(h1 @ e2^T + b) ======
// A (stripe-invariant) fragments hoisted to registers: 64 regs, loaded once.
#define STG_STRIDE 272
__global__ __launch_bounds__(512) void k_wgemm_tc(const float* __restrict__ e2b) {
    extern __shared__ char dyn[];
    char* pA = dyn;
    char* pB0 = dyn + 32768;
    char* pB1 = dyn + 65536;
    char* pStage = dyn + 98304;

    int tid = threadIdx.x, wid = tid >> 5, lane = tid & 31;
    int m0 = blockIdx.x * 128;
    int wm = wid & 3;
    int wn = wid >> 2;

    uint32_t uA = smem_u32(pA);
    uint32_t uB[2] = {smem_u32(pB0), smem_u32(pB1)};

    copy_sw512_async(uB[0], g_e2);
    CP_COMMIT();
    copy_sw512(pA, g_h1 + (size_t)m0 * 128);
    __syncthreads();                 // A visible to whole CTA

    int lrow = lane & 7;
    int lsel = lane >> 3;
    int a_row_off = (lsel & 1) * 8 + lrow;
    int a_chunk_sel = lsel >> 1;
    int b_row_off = (lsel >> 1) * 8 + lrow;
    int b_chunk_sel = lsel & 1;
    int g = lane >> 2, t4 = lane & 3;

    // hoist all A fragments (stripe-invariant): [ks][mt][4]
    uint32_t afr[8][2][4];
#pragma unroll
    for (int ks = 0; ks < 8; ks++) {
        int c0 = ks * 2;
#pragma unroll
        for (int mt = 0; mt < 2; mt++) {
            int row = wm * 32 + mt * 16 + a_row_off;
            int ch = c0 + a_chunk_sel;
            uint32_t addr = uA + row * 256 + (((ch ^ (row & 7)) & 15) << 4);
            ldsm_x4(afr[ks][mt][0], afr[ks][mt][1], afr[ks][mt][2], afr[ks][mt][3], addr);
        }
    }

    for (int s = 0; s < 32; s++) {
        CP_WAIT0();
        __syncthreads();             // B[s] visible; pStage drained
        if (s + 1 < 32) {
            copy_sw512_async(uB[(s + 1) & 1], g_e2 + (size_t)(s + 1) * 128 * 128);
            CP_COMMIT();
        }
        uint32_t uBc = uB[s & 1];

        float acc[2][4][4];
#pragma unroll
        for (int i = 0; i < 2; i++)
#pragma unroll
            for (int j = 0; j < 4; j++)
#pragma unroll
                for (int q = 0; q < 4; q++) acc[i][j][q] = 0.f;

#pragma unroll
        for (int ks = 0; ks < 8; ks++) {
            int c0 = ks * 2;
            uint32_t bfr[2][4];
#pragma unroll
            for (int bt = 0; bt < 2; bt++) {
                int row = wn * 32 + bt * 16 + b_row_off;
                int ch = c0 + b_chunk_sel;
                uint32_t addr = uBc + row * 256 + (((ch ^ (row & 7)) & 15) << 4);
                ldsm_x4(bfr[bt][0], bfr[bt][1], bfr[bt][2], bfr[bt][3], addr);
            }
#pragma unroll
            for (int mt = 0; mt < 2; mt++)
#pragma unroll
                for (int nt = 0; nt < 4; nt++)
                    mma16816(acc[mt][nt], afr[ks][mt], bfr[nt >> 1] + (nt & 1) * 2);
        }

#pragma unroll
        for (int mt = 0; mt < 2; mt++) {
            int r0 = wm * 32 + mt * 16 + g;
#pragma unroll
            for (int nt = 0; nt < 4; nt++) {
                int col = wn * 32 + nt * 8 + t4 * 2;
                float b0 = e2b[s * 128 + col], b1 = e2b[s * 128 + col + 1];
                __nv_bfloat162 v0 = __floats2bfloat162_rn(acc[mt][nt][0] + b0, acc[mt][nt][1] + b1);
                __nv_bfloat162 v1 = __floats2bfloat162_rn(acc[mt][nt][2] + b0, acc[mt][nt][3] + b1);
                *(__nv_bfloat162*)(pStage + r0 * STG_STRIDE + col * 2) = v0;
                *(__nv_bfloat162*)(pStage + (r0 + 8) * STG_STRIDE + col * 2) = v1;
            }
        }
        __syncthreads();
#pragma unroll
        for (int it = 0; it < 4; it++) {
            int i = tid + it * 512;
            int row = i >> 4, ch = i & 15;
            uint4 v = *(const uint4*)(pStage + row * STG_STRIDE + ch * 16);
            *(uint4*)((char*)(g_Wb + (size_t)(m0 + row) * 4096 + s * 128) + ch * 16) = v;
        }
    }
}

// ---------------- prep: lin0 + zero state ---------------------------------
__global__ void k_prep(const float* __restrict__ x, const float* __restrict__ W,
                       const float* __restrict__ b) {
    int idx = blockIdx.x * blockDim.x + threadIdx.x;
    if (idx < NN * DD) {
        int n = idx >> 6, o = idx & 63;
        const float* xr = x + n * 14;
        const float* wr = W + o * 14;
        float acc = b[o];
#pragma unroll
        for (int i = 0; i < 14; i++) acc += xr[i] * wr[i];
        g_out[idx] = fmaxf(acc, 0.f);
        g_agg[idx] = 0.f;
    }
    if (idx < NN) g_cnt[idx] = 0.f;
    if (idx < NB) g_gcnt[idx] = 0;
}

// ---- edge MLP layer 1 (bf16) + e2_W cast + small-weight transposes -------
#define EP_T1 (NE * 128)
#define EP_T2 (4096 * 128)
#define EP_T3 (12288 + 32768 + 16384 + 16384)
__global__ void k_edgeprep(const float* __restrict__ ea, const float* __restrict__ W,
                           const float* __restrict__ b, const float* __restrict__ e2W,
                           const float* __restrict__ gWih, const float* __restrict__ gWhh,
                           const float* __restrict__ lWih, const float* __restrict__ lWhh,
                           const float* __restrict__ fc1W) {
    int idx = blockIdx.x * blockDim.x + threadIdx.x;
    if (idx < EP_T1) {
        int e = idx >> 7, j = idx & 127;
        const float* er = ea + e * 4;
        const float* wr = W + j * 4;
        float acc = b[j];
#pragma unroll
        for (int i = 0; i < 4; i++) acc += er[i] * wr[i];
        g_h1[idx] = __float2bfloat16(fmaxf(acc, 0.f));
    } else if (idx < EP_T1 + EP_T2) {
        int k = idx - EP_T1;
        g_e2[k] = __float2bfloat16(e2W[k]);
    } else {
        int t = idx - EP_T1 - EP_T2;
        if (t < 12288) {
            int i = t / 192, gate = t % 192;
            g_gWihT[t] = gWih[gate * 64 + i];
            g_gWhhT[t] = gWhh[gate * 64 + i];
        } else if (t < 12288 + 32768) {
            int k = t - 12288;
            g_lWihTb[k] = __float2bfloat16(lWih[(k % 256) * 128 + k / 256]);
        } else if (t < 12288 + 32768 + 16384) {
            int k = t - 12288 - 32768;
            g_lWhhTb[k] = __float2bfloat16(lWhh[(k % 256) * 64 + k / 256]);
        } else if (t < EP_T3) {
            int k = t - 12288 - 32768 - 16384;
            g_fc1Tb[k] = __float2bfloat16(fc1W[(k % 128) * 128 + k / 128]);
        }
    }
}

// ---------------- counts (in-degree + graph sizes) ------------------------
__global__ void k_counts(const int* __restrict__ ei, const int* __restrict__ batch) {
    int i = blockIdx.x * blockDim.x + threadIdx.x;
    if (i < NE) atomicAdd(&g_cnt[ei[NE + i]], 1.f);
    if (i < NN) atomicAdd(&g_gcnt[batch[i]], 1);
}
__global__ void k_scan() {
    __shared__ int s[NB];
    int t = threadIdx.x;
    s[t] = g_gcnt[t];
    __syncthreads();
    for (int off = 1; off < NB; off <<= 1) {
        int v = (t >= off) ? s[t - off] : 0;
        __syncthreads();
        s[t] += v;
        __syncthreads();
    }
    g_gptr[t + 1] = s[t];
    if (t == 0) g_gptr[0] = 0;
}

// ---------------- messages: warp/edge, vectorized bf16 loads -------------
__global__ __launch_bounds__(256) void k_msg(const int* __restrict__ ei) {
    __shared__ float s[8][64];
    int tid = threadIdx.x, w = tid >> 5, l = tid & 31;
    int e0 = blockIdx.x * 8;
#pragma unroll
    for (int i = tid; i < 512; i += 256) {
        int el = i >> 6, c = i & 63;
        s[el][c] = g_out[ei[e0 + el] * 64 + c];
    }
    __syncthreads();
    int e = e0 + w;
    int dst = ei[NE + e];
    int co = (l & 7) * 8;
    int rb = l >> 3;
    float acc[8];
#pragma unroll
    for (int k = 0; k < 8; k++) acc[k] = 0.f;
    const __nv_bfloat16* Wr = g_Wb + (size_t)e * 4096;
#pragma unroll
    for (int r = 0; r < 16; r++) {
        int row = rb + r * 4;
        uint4 v = *(const uint4*)(Wr + row * 64 + co);
        float si = s[w][row];
        float2 f0 = __bfloat1622float2(*(__nv_bfloat162*)&v.x);
        float2 f1 = __bfloat1622float2(*(__nv_bfloat162*)&v.y);
        float2 f2 = __bfloat1622float2(*(__nv_bfloat162*)&v.z);
        float2 f3 = __bfloat1622float2(*(__nv_bfloat162*)&v.w);
        acc[0] += si * f0.x; acc[1] += si * f0.y;
        acc[2] += si * f1.x; acc[3] += si * f1.y;
        acc[4] += si * f2.x; acc[5] += si * f2.y;
        acc[6] += si * f3.x; acc[7] += si * f3.y;
    }
#pragma unroll
    for (int k = 0; k < 8; k++) {
        acc[k] += __shfl_xor_sync(0xffffffff, acc[k], 8);
        acc[k] += __shfl_xor_sync(0xffffffff, acc[k], 16);
    }
    int sub = l >> 3;
    atomicAdd(&g_agg[dst * 64 + co + sub * 2], acc[sub * 2]);
    atomicAdd(&g_agg[dst * 64 + co + sub * 2 + 1], acc[sub * 2 + 1]);
}

// ====== fused node update: m = relu(agg/cnt + h@rootW + cb); GRU ==========
#define ND_SMEM ((4096 + 2 * 64 * 66 + 2 * 16 * 192) * 4)
__global__ __launch_bounds__(256) void k_nodeup(const float* __restrict__ rootW,
                                                const float* __restrict__ convb,
                                                const float* __restrict__ bih,
                                                const float* __restrict__ bhh) {
    extern __shared__ float sdyn[];
    float* sW = sdyn;                       // 4096
    float* sm_ = sdyn + 4096;               // 64 x 66
    float* sh_ = sm_ + 64 * 66;             // 64 x 66
    float* sgi = sh_ + 64 * 66;             // 16 x 192
    float* sgh = sgi + 16 * 192;            // 16 x 192
    int tid = threadIdx.x;
    int base = blockIdx.x * 64;

    for (int i = tid; i < 4096; i += 256) {
        sW[i] = rootW[i];
        int n = i >> 6, c = i & 63;
        sh_[n * 66 + c] = g_out[(base + n) * 64 + c];
    }
    __syncthreads();

    {
        int o = tid & 63, ln = tid >> 6;
        float cb = convb[o];
        for (int g4 = 0; g4 < 16; g4++) {
            int n = g4 * 4 + ln;
            const float* hr = sh_ + n * 66;
            float acc = 0.f;
#pragma unroll
            for (int i = 0; i < 64; i++) acc += hr[i] * sW[i * 64 + o];
            int node = base + n;
            float c = g_cnt[node];
            if (c < 1.f) c = 1.f;
            float v = g_agg[node * 64 + o] / c + acc + cb;
            g_agg[node * 64 + o] = 0.f;
            sm_[n * 66 + o] = fmaxf(v, 0.f);
        }
    }
    __syncthreads();

    int gg = (tid % 48) * 4;
    int ng = (tid / 48) * 4;
    for (int nb = 0; nb < 4; nb++) {
        int nbase = nb * 16;
        if (tid < 192) {
            float accI[4][4], accH[4][4];
#pragma unroll
            for (int n = 0; n < 4; n++)
#pragma unroll
                for (int q = 0; q < 4; q++) { accI[n][q] = 0.f; accH[n][q] = 0.f; }
#pragma unroll 4
            for (int i = 0; i < 64; i++) {
                float4 wI = *(const float4*)(g_gWihT + i * 192 + gg);
                float4 wH = *(const float4*)(g_gWhhT + i * 192 + gg);
#pragma unroll
                for (int n = 0; n < 4; n++) {
                    float mi = sm_[(nbase + ng + n) * 66 + i];
                    float hi = sh_[(nbase + ng + n) * 66 + i];
                    accI[n][0] += mi * wI.x; accI[n][1] += mi * wI.y;
                    accI[n][2] += mi * wI.z; accI[n][3] += mi * wI.w;
                    accH[n][0] += hi * wH.x; accH[n][1] += hi * wH.y;
                    accH[n][2] += hi * wH.z; accH[n][3] += hi * wH.w;
                }
            }
            float4 bi = *(const float4*)(bih + gg);
            float4 bh = *(const float4*)(bhh + gg);
#pragma unroll
            for (int n = 0; n < 4; n++) {
                float* pi = sgi + (ng + n) * 192 + gg;
                float* ph = sgh + (ng + n) * 192 + gg;
                pi[0] = accI[n][0] + bi.x; pi[1] = accI[n][1] + bi.y;
                pi[2] = accI[n][2] + bi.z; pi[3] = accI[n][3] + bi.w;
                ph[0] = accH[n][0] + bh.x; ph[1] = accH[n][1] + bh.y;
                ph[2] = accH[n][2] + bh.z; ph[3] = accH[n][3] + bh.w;
            }
        }
        __syncthreads();
        for (int i = tid; i < 1024; i += 256) {
            int n = i >> 6, c = i & 63;
            float r = sigmoidf_(sgi[n * 192 + c] + sgh[n * 192 + c]);
            float z = sigmoidf_(sgi[n * 192 + 64 + c] + sgh[n * 192 + 64 + c]);
            float nn2 = tanhf(sgi[n * 192 + 128 + c] + r * sgh[n * 192 + 128 + c]);
            float hnew = (1.f - z) * nn2 + z * sh_[(nbase + n) * 66 + c];
            g_out[(base + nbase + n) * 64 + c] = hnew;
        }
        __syncthreads();
    }
}

// ====== fused Set2Set (3 steps) + final head; block = 1 graph =============
// LSTM/fc1 weights bf16 (131 KB total -> L1-resident across the 3 steps).
__global__ __launch_bounds__(256) void k_s2s(const float* __restrict__ lbih,
                                             const float* __restrict__ lbhh,
                                             const float* __restrict__ fc1b,
                                             const float* __restrict__ fc2W,
                                             const float* __restrict__ fc2b,
                                             float* __restrict__ outp) {
    __shared__ float qstar[128], shl[64], scl[64], sg[256], sa[256];
    int g = blockIdx.x, j = threadIdx.x;
    int s = g_gptr[g], e2 = g_gptr[g + 1];
    int cnt = e2 - s;
    if (j < 128) qstar[j] = 0.f;
    if (j < 64) { shl[j] = 0.f; scl[j] = 0.f; }
    __syncthreads();

    for (int step = 0; step < 3; step++) {
        float acc = lbih[j] + lbhh[j];
#pragma unroll 8
        for (int k = 0; k < 128; k++)
            acc += qstar[k] * __bfloat162float(g_lWihTb[k * 256 + j]);
#pragma unroll 8
        for (int k = 0; k < 64; k++)
            acc += shl[k] * __bfloat162float(g_lWhhTb[k * 256 + j]);
        sg[j] = acc;
        __syncthreads();
        if (j < 64) {
            float i_ = sg[j], f_ = sg[64 + j], gg_ = sg[128 + j], o_ = sg[192 + j];
            float c = sigmoidf_(f_) * scl[j] + sigmoidf_(i_) * tanhf(gg_);
            float h = sigmoidf_(o_) * tanhf(c);
            scl[j] = c;
            shl[j] = h;
        }
        __syncthreads();
        float mymax = -3.0e38f;
        for (int n = j; n < cnt; n += 256) {
            const float* orow = g_out + (size_t)(s + n) * 64;
            float d = 0.f;
#pragma unroll
            for (int i = 0; i < 64; i++) d += orow[i] * shl[i];
            sa[n] = d;
            mymax = fmaxf(mymax, d);
        }
        sg[j] = mymax;
        __syncthreads();
        for (int st = 128; st > 0; st >>= 1) {
            if (j < st) sg[j] = fmaxf(sg[j], sg[j + st]);
            __syncthreads();
        }
        float mx = sg[0];
        __syncthreads();
        float mysum = 0.f;
        for (int n = j; n < cnt; n += 256) {
            float ex = expf(sa[n] - mx);
            sa[n] = ex;
            mysum += ex;
        }
        sg[j] = mysum;
        __syncthreads();
        for (int st = 128; st > 0; st >>= 1) {
            if (j < st) sg[j] += sg[j + st];
            __syncthreads();
        }
        float den = sg[0];
        __syncthreads();
        if (j < 64) {
            float r = 0.f;
            for (int n = 0; n < cnt; n++) r += sa[n] * g_out[(size_t)(s + n) * 64 + j];
            if (cnt > 0) r /= den;
            qstar[j] = shl[j];
            qstar[64 + j] = r;
        }
        __syncthreads();
    }

    float val = 0.f;
    if (j < 128) {
        float a = fc1b[j];
#pragma unroll 8
        for (int k = 0; k < 128; k++)
            a += qstar[k] * __bfloat162float(g_fc1Tb[k * 128 + j]);
        val = fmaxf(a, 0.f) * fc2W[j];
    }
    sg[j] = val;
    __syncthreads();
    for (int st = 128; st > 0; st >>= 1) {
        if (j < st) sg[j] += sg[j + st];
        __syncthreads();
    }
    if (j == 0) outp[g] = sg[0] + fc2b[0];
}

// ---------------- host: launch sequence ----------------------------------
extern "C" void kernel_launch(void* const* d_in, const int* in_sizes, int n_in,
                              void* d_out, int out_size) {
    const float* x       = (const float*)d_in[0];
    const int*   ei      = (const int*)d_in[1];
    const float* ea      = (const float*)d_in[2];
    const int*   batch   = (const int*)d_in[3];
    const float* lin0_W  = (const float*)d_in[4];
    const float* lin0_b  = (const float*)d_in[5];
    const float* e1_W    = (const float*)d_in[6];
    const float* e1_b    = (const float*)d_in[7];
    const float* e2_W    = (const float*)d_in[8];
    const float* e2_b    = (const float*)d_in[9];
    const float* root_W  = (const float*)d_in[10];
    const float* conv_b  = (const float*)d_in[11];
    const float* gru_Wih = (const float*)d_in[12];
    const float* gru_Whh = (const float*)d_in[13];
    const float* gru_bih = (const float*)d_in[14];
    const float* gru_bhh = (const float*)d_in[15];
    const float* lstm_Wih = (const float*)d_in[16];
    const float* lstm_Whh = (const float*)d_in[17];
    const float* lstm_bih = (const float*)d_in[18];
    const float* lstm_bhh = (const float*)d_in[19];
    const float* fc1_W   = (const float*)d_in[20];
    const float* fc1_b   = (const float*)d_in[21];
    const float* fc2_W   = (const float*)d_in[22];
    const float* fc2_b   = (const float*)d_in[23];
    float* outp = (float*)d_out;

    static bool attr_set = false;
    const int WG_SMEM = 98304 + 128 * STG_STRIDE;    // 133,120 B
    if (!attr_set) {
        cudaFuncSetAttribute(k_wgemm_tc, cudaFuncAttributeMaxDynamicSharedMemorySize, WG_SMEM);
        cudaFuncSetAttribute(k_nodeup, cudaFuncAttributeMaxDynamicSharedMemorySize, ND_SMEM);
        attr_set = true;
    }

    // k_wgemm_tc in slot #4 — the launch position ncu's window captures.
    k_prep<<<(NN * DD) / 256, 256>>>(x, lin0_W, lin0_b);
    k_edgeprep<<<(EP_T1 + EP_T2 + EP_T3 + 255) / 256, 256>>>(
        ea, e1_W, e1_b, e2_W, gru_Wih, gru_Whh, lstm_Wih, lstm_Whh, fc1_W);
    k_counts<<<NE / 256, 256>>>(ei, batch);
    k_wgemm_tc<<<NE / 128, 512, WG_SMEM>>>(e2_b);
    k_scan<<<1, NB>>>();

    for (int it = 0; it < 3; it++) {
        k_msg<<<NE / 8, 256>>>(ei);
        k_nodeup<<<NN / 64, 256, ND_SMEM>>>(root_W, conv_b, gru_bih, gru_bhh);
    }

    k_s2s<<<NB, 256>>>(lstm_bih, lstm_bhh, fc1_b, fc2_W, fc2_b, outp);
}